// round 4
// baseline (speedup 1.0000x reference)
#include <cuda_runtime.h>
#include <cuda_bf16.h>
#include <cstdint>
#include <cstddef>

#define SEQ 1024
#define EMB 1024
#define BATCH 4
#define NH 16
#define DH 64
#define BH (BATCH*NH)

#define SKW 20      // SMEM tile row stride (words): 16 data + 4 pad, conflict-free for mma frags
#define SSTR 1032   // score-row stride in floats (1024 + 8 pad)

// ---- scratch (no device allocations allowed) ----
__device__ float g_V  [(size_t)BATCH*SEQ*EMB];
__device__ float g_ctx[(size_t)BATCH*SEQ*EMB];
__device__ __nv_bfloat16 g_Qh [(size_t)BATCH*SEQ*EMB];
__device__ __nv_bfloat16 g_Ql [(size_t)BATCH*SEQ*EMB];
__device__ __nv_bfloat16 g_Kh [(size_t)BATCH*SEQ*EMB];
__device__ __nv_bfloat16 g_Kl [(size_t)BATCH*SEQ*EMB];
__device__ __nv_bfloat16 g_Vth[(size_t)BATCH*SEQ*EMB];
__device__ __nv_bfloat16 g_Vtl[(size_t)BATCH*SEQ*EMB];

// ============================================================
// warp MMA m16n8k16 bf16 -> fp32
// ============================================================
__device__ __forceinline__ void mma16816(float* c, const uint32_t a[4], const uint32_t b[2]){
    asm volatile("mma.sync.aligned.m16n8k16.row.col.f32.bf16.bf16.f32 "
        "{%0,%1,%2,%3}, {%4,%5,%6,%7}, {%8,%9}, {%0,%1,%2,%3};"
        : "+f"(c[0]), "+f"(c[1]), "+f"(c[2]), "+f"(c[3])
        : "r"(a[0]), "r"(a[1]), "r"(a[2]), "r"(a[3]), "r"(b[0]), "r"(b[1]));
}

// 8 fp32 -> bf16 hi/lo packed words
__device__ __forceinline__ void cvt8v(float4 x0, float4 x1, uint4& h, uint4& l){
    float x[8] = {x0.x,x0.y,x0.z,x0.w,x1.x,x1.y,x1.z,x1.w};
    uint32_t hw[8], lw[8];
#pragma unroll
    for (int j = 0; j < 8; j++){
        __nv_bfloat16 hb = __float2bfloat16(x[j]);
        float hf = __bfloat162float(hb);
        __nv_bfloat16 lb = __float2bfloat16(x[j] - hf);
        hw[j] = (uint32_t)__bfloat16_as_ushort(hb);
        lw[j] = (uint32_t)__bfloat16_as_ushort(lb);
    }
    h.x = hw[0]|(hw[1]<<16); h.y = hw[2]|(hw[3]<<16);
    h.z = hw[4]|(hw[5]<<16); h.w = hw[6]|(hw[7]<<16);
    l.x = lw[0]|(lw[1]<<16); l.y = lw[2]|(lw[3]<<16);
    l.z = lw[4]|(lw[5]<<16); l.w = lw[6]|(lw[7]<<16);
}

// one BK=32 chunk of bf16x3 MMAs (validated R3)
template<int MT, int NT>
__device__ __forceinline__ void mma_chunk(float acc[MT][NT][4],
    const uint32_t* __restrict__ sAh, const uint32_t* __restrict__ sAl,
    const uint32_t* __restrict__ sBh, const uint32_t* __restrict__ sBl,
    int mof, int nof, int lane)
{
    const int r = lane >> 2, w = lane & 3;
#pragma unroll
    for (int ks = 0; ks < 2; ks++){
        const int kw = ks*8 + w;
        uint32_t ah[MT][4], al[MT][4], bh[NT][2], bl[NT][2];
#pragma unroll
        for (int mi = 0; mi < MT; mi++){
            int base = (mof + mi*16 + r)*SKW + kw;
            ah[mi][0] = sAh[base];     ah[mi][1] = sAh[base + 8*SKW];
            ah[mi][2] = sAh[base + 4]; ah[mi][3] = sAh[base + 8*SKW + 4];
            al[mi][0] = sAl[base];     al[mi][1] = sAl[base + 8*SKW];
            al[mi][2] = sAl[base + 4]; al[mi][3] = sAl[base + 8*SKW + 4];
        }
#pragma unroll
        for (int ni = 0; ni < NT; ni++){
            int base = (nof + ni*8 + r)*SKW + kw;
            bh[ni][0] = sBh[base]; bh[ni][1] = sBh[base + 4];
            bl[ni][0] = sBl[base]; bl[ni][1] = sBl[base + 4];
        }
#pragma unroll
        for (int mi = 0; mi < MT; mi++)
#pragma unroll
            for (int ni = 0; ni < NT; ni++){
                mma16816(acc[mi][ni], ah[mi], bh[ni]);
                mma16816(acc[mi][ni], ah[mi], bl[ni]);
                mma16816(acc[mi][ni], al[mi], bh[ni]);
            }
    }
}

__device__ __forceinline__ void store_hl(__nv_bfloat16* H, __nv_bfloat16* L,
                                         size_t off, float2 v){
    __nv_bfloat16 hx = __float2bfloat16(v.x), hy = __float2bfloat16(v.y);
    __nv_bfloat162 hp; hp.x = hx; hp.y = hy;
    __nv_bfloat162 lp;
    lp.x = __float2bfloat16(v.x - __bfloat162float(hx));
    lp.y = __float2bfloat16(v.y - __bfloat162float(hy));
    *(__nv_bfloat162*)(H + off) = hp;
    *(__nv_bfloat162*)(L + off) = lp;
}

// ============================================================
// NT GEMM with register-staged prefetch:
// C[M,N] = A[M,K] @ W[N,K]^T + bias. CTA 128x128, warp tile 64x32.
// OB=true: write bf16 hi/lo planes; else fp32.
// ============================================================
template<bool OB>
__global__ __launch_bounds__(256, 1)
void gemm_proj(const float* __restrict__ A, const float* __restrict__ W,
               const float* __restrict__ bias, float* __restrict__ C,
               __nv_bfloat16* __restrict__ Ch, __nv_bfloat16* __restrict__ Cl,
               int M, int N, int K)
{
    __shared__ uint32_t sAh[128*SKW], sAl[128*SKW], sBh[128*SKW], sBl[128*SKW];
    const int tid = threadIdx.x, wid = tid >> 5, lane = tid & 31;
    const int wm = (wid >> 2)*64, wn = (wid & 3)*32;
    const int bm = blockIdx.y*128, bn = blockIdx.x*128;
    const int r0 = tid >> 2, s0 = tid & 3;     // seg rows r0, r0+64

    float acc[4][4][4];
#pragma unroll
    for (int i = 0; i < 4; i++)
#pragma unroll
        for (int j = 0; j < 4; j++)
#pragma unroll
            for (int k = 0; k < 4; k++) acc[i][j][k] = 0.f;

    const float* pA0 = A + (size_t)(bm + r0)*K + s0*8;
    const float* pA1 = A + (size_t)(bm + r0 + 64)*K + s0*8;
    const float* pB0 = W + (size_t)(bn + r0)*K + s0*8;
    const float* pB1 = W + (size_t)(bn + r0 + 64)*K + s0*8;

    float4 a00,a01,a10,a11,b00,b01,b10,b11;
    // LD chunk 0
    a00 = *(const float4*)(pA0); a01 = *(const float4*)(pA0+4);
    a10 = *(const float4*)(pA1); a11 = *(const float4*)(pA1+4);
    b00 = *(const float4*)(pB0); b01 = *(const float4*)(pB0+4);
    b10 = *(const float4*)(pB1); b11 = *(const float4*)(pB1+4);

    const int nch = K >> 5;
    for (int c = 0; c < nch; c++){
        __syncthreads();
        {
            uint4 h, l;
            cvt8v(a00, a01, h, l);
            *(uint4*)(sAh + r0*SKW + s0*4) = h;        *(uint4*)(sAl + r0*SKW + s0*4) = l;
            cvt8v(a10, a11, h, l);
            *(uint4*)(sAh + (r0+64)*SKW + s0*4) = h;   *(uint4*)(sAl + (r0+64)*SKW + s0*4) = l;
            cvt8v(b00, b01, h, l);
            *(uint4*)(sBh + r0*SKW + s0*4) = h;        *(uint4*)(sBl + r0*SKW + s0*4) = l;
            cvt8v(b10, b11, h, l);
            *(uint4*)(sBh + (r0+64)*SKW + s0*4) = h;   *(uint4*)(sBl + (r0+64)*SKW + s0*4) = l;
        }
        __syncthreads();
        if (c + 1 < nch){
            int off = (c+1)*32;
            a00 = *(const float4*)(pA0+off); a01 = *(const float4*)(pA0+off+4);
            a10 = *(const float4*)(pA1+off); a11 = *(const float4*)(pA1+off+4);
            b00 = *(const float4*)(pB0+off); b01 = *(const float4*)(pB0+off+4);
            b10 = *(const float4*)(pB1+off); b11 = *(const float4*)(pB1+off+4);
        }
        mma_chunk<4,4>(acc, sAh, sAl, sBh, sBl, wm, wn, lane);
    }

    const int r = lane >> 2, cl = (lane & 3)*2;
#pragma unroll
    for (int mi = 0; mi < 4; mi++){
#pragma unroll
        for (int ni = 0; ni < 4; ni++){
            int row = bm + wm + mi*16 + r;
            int col = bn + wn + ni*8 + cl;
            float2 bv = *(const float2*)(bias + col);
            float2 o0, o1;
            o0.x = acc[mi][ni][0] + bv.x; o0.y = acc[mi][ni][1] + bv.y;
            o1.x = acc[mi][ni][2] + bv.x; o1.y = acc[mi][ni][3] + bv.y;
            if (OB){
                store_hl(Ch, Cl, (size_t)row*N + col, o0);
                store_hl(Ch, Cl, (size_t)(row+8)*N + col, o1);
            } else {
                *(float2*)(C + (size_t)row*N + col)     = o0;
                *(float2*)(C + (size_t)(row+8)*N + col) = o1;
            }
        }
    }
}

// ============================================================
// V transpose + hi/lo split: Vt[b][e][s] = split(V[b][s][e])
// ============================================================
__global__ void transpose_k(const float* __restrict__ V,
                            __nv_bfloat16* __restrict__ Vth,
                            __nv_bfloat16* __restrict__ Vtl)
{
    __shared__ float tile[32][33];
    const int b = blockIdx.z;
    const int e0 = blockIdx.x*32, s0 = blockIdx.y*32;
    const int tx = threadIdx.x, ty = threadIdx.y;
    const float* src = V + (size_t)b*SEQ*EMB;
#pragma unroll
    for (int i = 0; i < 32; i += 8)
        tile[ty + i][tx] = src[(size_t)(s0 + ty + i)*EMB + e0 + tx];
    __syncthreads();
#pragma unroll
    for (int i = 0; i < 32; i += 8){
        float v = tile[tx][ty + i];
        __nv_bfloat16 hb = __float2bfloat16(v);
        size_t off = ((size_t)b*EMB + e0 + ty + i)*SEQ + s0 + tx;
        Vth[off] = hb;
        Vtl[off] = __float2bfloat16(v - __bfloat162float(hb));
    }
}

__global__ void zero_kernel(float4* p, int n4){
    int i = blockIdx.x*blockDim.x + threadIdx.x;
    if (i < n4) p[i] = make_float4(0.f, 0.f, 0.f, 0.f);
}

// ============================================================
// FUSED attention: scores(bf16x3) + mask + softmax + avg(atomic) + P.V(bf16x3)
// CTA per (q-tile of 32, bh). 256 threads.
// ============================================================
#define W_SS  (32*SSTR)          // 33024
#define W_Q   (2*32*SKW)         // 1280 per plane (also reused for P chunks)
#define W_K   (2*128*SKW)        // 5120 per plane (also reused for V chunks)
#define SMEMF ((W_SS + 2*W_Q + 2*W_K)*4)   // 183296 bytes

__global__ __launch_bounds__(256, 1)
void fused_attn(const __nv_bfloat16* __restrict__ Qh, const __nv_bfloat16* __restrict__ Ql,
                const __nv_bfloat16* __restrict__ Kh, const __nv_bfloat16* __restrict__ Kl,
                const __nv_bfloat16* __restrict__ Vth, const __nv_bfloat16* __restrict__ Vtl,
                const int* __restrict__ mask, float* __restrict__ avg,
                float* __restrict__ ctx)
{
    extern __shared__ float dynsm[];
    float*    sS  = dynsm;
    uint32_t* sQh = (uint32_t*)(dynsm + W_SS);
    uint32_t* sQl = sQh + W_Q;
    uint32_t* sKh = sQl + W_Q;
    uint32_t* sKl = sKh + W_K;

    const int tid = threadIdx.x, wid = tid >> 5, lane = tid & 31;
    const int q0 = blockIdx.x*32;
    const int bh = blockIdx.y, b = bh >> 4, h = bh & 15;
    const int wm = (wid >> 2)*16;
    const int r = lane >> 2, cl = (lane & 3)*2;

    // ---- copy Q tile (32 x 64 bf16, 2 chunks) ----
    {
        int u = tid;                         // 256 units of 8 bf16
        int ch = u >> 7, row = (u >> 2) & 31, s = u & 3;
        size_t g = ((size_t)(b*SEQ + q0 + row))*EMB + h*DH + ch*32 + s*8;
        *(uint4*)(sQh + ch*(32*SKW) + row*SKW + s*4) = *(const uint4*)(Qh + g);
        *(uint4*)(sQl + ch*(32*SKW) + row*SKW + s*4) = *(const uint4*)(Ql + g);
    }

    // ---- scores: loop 8 n-tiles of 128 key positions ----
    const int wn = (wid & 3)*32;
    for (int nt = 0; nt < 8; nt++){
        const int n0 = nt*128;
        __syncthreads();
#pragma unroll
        for (int i = 0; i < 4; i++){
            int u = tid + i*256;             // 1024 units
            int ch = u >> 9, row = (u >> 2) & 127, s = u & 3;
            size_t g = ((size_t)(b*SEQ + n0 + row))*EMB + h*DH + ch*32 + s*8;
            *(uint4*)(sKh + ch*(128*SKW) + row*SKW + s*4) = *(const uint4*)(Kh + g);
            *(uint4*)(sKl + ch*(128*SKW) + row*SKW + s*4) = *(const uint4*)(Kl + g);
        }
        __syncthreads();

        float acc[1][4][4];
#pragma unroll
        for (int j = 0; j < 4; j++)
#pragma unroll
            for (int k = 0; k < 4; k++) acc[0][j][k] = 0.f;
#pragma unroll
        for (int ch = 0; ch < 2; ch++)
            mma_chunk<1,4>(acc, sQh + ch*(32*SKW), sQl + ch*(32*SKW),
                           sKh + ch*(128*SKW), sKl + ch*(128*SKW), wm, wn, lane);

        // epilogue: mask + scale -> sS
#pragma unroll
        for (int ni = 0; ni < 4; ni++){
            int col = wn + ni*8 + cl;        // 0..127 within tile
            int gcol = n0 + col;
#pragma unroll
            for (int half = 0; half < 2; half++){
                int qr = wm + r + half*8;    // 0..31
                int2 m = *(const int2*)(mask + ((size_t)(b*SEQ + q0 + qr))*SEQ + gcol);
                float2 o;
                o.x = (m.x == 0) ? -1e9f : acc[0][ni][half*2+0]*0.125f;
                o.y = (m.y == 0) ? -1e9f : acc[0][ni][half*2+1]*0.125f;
                *(float2*)(sS + qr*SSTR + gcol) = o;
            }
        }
    }
    __syncthreads();

    // ---- softmax over sS rows + atomicAdd head-average ----
    {
        const int row = tid >> 3, j = tid & 7;   // 8 threads per row
        float* rp = sS + row*SSTR + j*4;
        float mx = -3.0e38f;
#pragma unroll
        for (int i = 0; i < 32; i++){
            float4 v = *(const float4*)(rp + i*32);
            mx = fmaxf(mx, fmaxf(fmaxf(v.x, v.y), fmaxf(v.z, v.w)));
        }
        mx = fmaxf(mx, __shfl_xor_sync(0xffffffffu, mx, 1));
        mx = fmaxf(mx, __shfl_xor_sync(0xffffffffu, mx, 2));
        mx = fmaxf(mx, __shfl_xor_sync(0xffffffffu, mx, 4));

        float sum = 0.f;
#pragma unroll
        for (int i = 0; i < 32; i++){
            float4 v = *(const float4*)(rp + i*32);
            v.x = __expf(v.x - mx); v.y = __expf(v.y - mx);
            v.z = __expf(v.z - mx); v.w = __expf(v.w - mx);
            *(float4*)(rp + i*32) = v;
            sum += v.x + v.y + v.z + v.w;
        }
        sum += __shfl_xor_sync(0xffffffffu, sum, 1);
        sum += __shfl_xor_sync(0xffffffffu, sum, 2);
        sum += __shfl_xor_sync(0xffffffffu, sum, 4);

        const float inv = 1.0f / sum;
        float* ab = avg + ((size_t)(b*SEQ + q0 + row))*SEQ + j*4;
#pragma unroll
        for (int i = 0; i < 32; i++){
            float4 v = *(const float4*)(rp + i*32);
            v.x *= inv; v.y *= inv; v.z *= inv; v.w *= inv;
            *(float4*)(rp + i*32) = v;
            atomicAdd(ab + i*32 + 0, v.x*0.0625f);
            atomicAdd(ab + i*32 + 1, v.y*0.0625f);
            atomicAdd(ab + i*32 + 2, v.z*0.0625f);
            atomicAdd(ab + i*32 + 3, v.w*0.0625f);
        }
    }

    // ---- ctx = P @ V : 32 BK=32 chunks, P from sS, V from bf16 planes ----
    const int wn2 = (wid & 3)*16;
    float accc[1][2][4];
#pragma unroll
    for (int j = 0; j < 2; j++)
#pragma unroll
        for (int k = 0; k < 4; k++) accc[0][j][k] = 0.f;

    for (int c = 0; c < 32; c++){
        __syncthreads();
        if (tid < 128){
            int row = tid >> 2, s = tid & 3;
            const float* p = sS + row*SSTR + c*32 + s*8;
            uint4 hh, ll;
            cvt8v(*(const float4*)p, *(const float4*)(p+4), hh, ll);
            *(uint4*)(sQh + row*SKW + s*4) = hh;
            *(uint4*)(sQl + row*SKW + s*4) = ll;
        }
        {
            int row = tid >> 2, s = tid & 3;      // 64 rows x 4 segs
            size_t g = ((size_t)(b*EMB + h*DH + row))*SEQ + c*32 + s*8;
            *(uint4*)(sKh + row*SKW + s*4) = *(const uint4*)(Vth + g);
            *(uint4*)(sKl + row*SKW + s*4) = *(const uint4*)(Vtl + g);
        }
        __syncthreads();
        mma_chunk<1,2>(accc, sQh, sQl, sKh, sKl, wm, wn2, lane);
    }

    // ctx epilogue
#pragma unroll
    for (int ni = 0; ni < 2; ni++){
        int col = h*DH + wn2 + ni*8 + cl;
        int q = q0 + wm + r;
        float2 o0, o1;
        o0.x = accc[0][ni][0]; o0.y = accc[0][ni][1];
        o1.x = accc[0][ni][2]; o1.y = accc[0][ni][3];
        *(float2*)(ctx + ((size_t)(b*SEQ + q))*EMB + col)     = o0;
        *(float2*)(ctx + ((size_t)(b*SEQ + q + 8))*EMB + col) = o1;
    }
}

// ============================================================
extern "C" void kernel_launch(void* const* d_in, const int* in_sizes, int n_in,
                              void* d_out, int out_size)
{
    const float* query = (const float*)d_in[0];
    const float* key   = (const float*)d_in[1];
    const float* value = (const float*)d_in[2];
    const int*   mask  = (const int*)  d_in[3];
    const float* Wq = (const float*)d_in[4];
    const float* bq = (const float*)d_in[5];
    const float* Wk = (const float*)d_in[6];
    const float* bk = (const float*)d_in[7];
    const float* Wv = (const float*)d_in[8];
    const float* bv = (const float*)d_in[9];
    const float* Wo = (const float*)d_in[10];
    const float* bo = (const float*)d_in[11];

    float* out      = (float*)d_out;
    float* attn_avg = out + (size_t)BATCH*SEQ*EMB;

    float *V, *CTX;
    __nv_bfloat16 *QH, *QL, *KH, *KL, *VTH, *VTL;
    cudaGetSymbolAddress((void**)&V,   g_V);
    cudaGetSymbolAddress((void**)&CTX, g_ctx);
    cudaGetSymbolAddress((void**)&QH,  g_Qh);
    cudaGetSymbolAddress((void**)&QL,  g_Ql);
    cudaGetSymbolAddress((void**)&KH,  g_Kh);
    cudaGetSymbolAddress((void**)&KL,  g_Kl);
    cudaGetSymbolAddress((void**)&VTH, g_Vth);
    cudaGetSymbolAddress((void**)&VTL, g_Vtl);

    cudaFuncSetAttribute(fused_attn, cudaFuncAttributeMaxDynamicSharedMemorySize, SMEMF);

    const int M = BATCH*SEQ;   // 4096
    dim3 gproj(EMB/128, M/128);

    gemm_proj<true><<<gproj, 256>>>(query, Wq, bq, nullptr, QH, QL, M, EMB, EMB);
    gemm_proj<true><<<gproj, 256>>>(key,   Wk, bk, nullptr, KH, KL, M, EMB, EMB);
    gemm_proj<false><<<gproj, 256>>>(value, Wv, bv, V, nullptr, nullptr, M, EMB, EMB);

    transpose_k<<<dim3(EMB/32, SEQ/32, BATCH), dim3(32, 8)>>>(V, VTH, VTL);

    {
        int n4 = (int)((size_t)BATCH*SEQ*SEQ/4);
        zero_kernel<<<(n4 + 255)/256, 256>>>((float4*)attn_avg, n4);
    }

    fused_attn<<<dim3(SEQ/32, BH), 256, SMEMF>>>(QH, QL, KH, KL, VTH, VTL,
                                                 mask, attn_avg, CTX);

    gemm_proj<false><<<gproj, 256>>>(CTX, Wo, bo, out, nullptr, nullptr, M, EMB, EMB);
}

// round 5
// speedup vs baseline: 1.4451x; 1.4451x over previous
#include <cuda_runtime.h>
#include <cuda_bf16.h>
#include <cstdint>
#include <cstddef>

#define SEQ 1024
#define EMB 1024
#define BATCH 4
#define NH 16
#define DH 64
#define BH (BATCH*NH)
#define SS ((size_t)SEQ*(size_t)SEQ)

#define SKW 20            // SMEM row stride (words): 16 data + 4 pad, conflict-free for mma frags
#define GPLANE (128*SKW)  // 2560 words: one 128x32 bf16 plane
#define BPLN   (64*SKW)   // 1280 words: one 64x32 bf16 plane
#define SCPLANE (2*GPLANE)        // scores: 2 K-chunks per operand plane
#define CTXBUF (2*GPLANE + 2*BPLN) // ctx per-buffer words (Ah,Al,Bh,Bl)

// ---- scratch (no device allocations allowed) ----
__device__ float g_V  [(size_t)BATCH*SEQ*EMB];
__device__ float g_ctx[(size_t)BATCH*SEQ*EMB];
__device__ float g_attn[(size_t)BH*SEQ*SEQ];   // raw masked scores, 268 MB
__device__ float2 g_stats[(size_t)BH*SEQ];     // (rowmax, 1/rowsum)
__device__ __nv_bfloat16 g_Qh [(size_t)BATCH*SEQ*EMB];
__device__ __nv_bfloat16 g_Ql [(size_t)BATCH*SEQ*EMB];
__device__ __nv_bfloat16 g_Kh [(size_t)BATCH*SEQ*EMB];
__device__ __nv_bfloat16 g_Kl [(size_t)BATCH*SEQ*EMB];
__device__ __nv_bfloat16 g_Vth[(size_t)BATCH*SEQ*EMB];
__device__ __nv_bfloat16 g_Vtl[(size_t)BATCH*SEQ*EMB];

// ============================================================
// warp MMA m16n8k16 bf16 -> fp32
// ============================================================
__device__ __forceinline__ void mma16816(float* c, const uint32_t a[4], const uint32_t b[2]){
    asm volatile("mma.sync.aligned.m16n8k16.row.col.f32.bf16.bf16.f32 "
        "{%0,%1,%2,%3}, {%4,%5,%6,%7}, {%8,%9}, {%0,%1,%2,%3};"
        : "+f"(c[0]), "+f"(c[1]), "+f"(c[2]), "+f"(c[3])
        : "r"(a[0]), "r"(a[1]), "r"(a[2]), "r"(a[3]), "r"(b[0]), "r"(b[1]));
}

// 8 fp32 -> bf16 hi/lo packed words
__device__ __forceinline__ void cvt8v(float4 x0, float4 x1, uint4& h, uint4& l){
    float x[8] = {x0.x,x0.y,x0.z,x0.w,x1.x,x1.y,x1.z,x1.w};
    uint32_t hw[8], lw[8];
#pragma unroll
    for (int j = 0; j < 8; j++){
        __nv_bfloat16 hb = __float2bfloat16(x[j]);
        float hf = __bfloat162float(hb);
        __nv_bfloat16 lb = __float2bfloat16(x[j] - hf);
        hw[j] = (uint32_t)__bfloat16_as_ushort(hb);
        lw[j] = (uint32_t)__bfloat16_as_ushort(lb);
    }
    h.x = hw[0]|(hw[1]<<16); h.y = hw[2]|(hw[3]<<16);
    h.z = hw[4]|(hw[5]<<16); h.w = hw[6]|(hw[7]<<16);
    l.x = lw[0]|(lw[1]<<16); l.y = lw[2]|(lw[3]<<16);
    l.z = lw[4]|(lw[5]<<16); l.w = lw[6]|(lw[7]<<16);
}

// one BK=32 chunk of bf16x3 MMAs (validated R3/R4)
template<int MT, int NT>
__device__ __forceinline__ void mma_chunk(float acc[MT][NT][4],
    const uint32_t* __restrict__ sAh, const uint32_t* __restrict__ sAl,
    const uint32_t* __restrict__ sBh, const uint32_t* __restrict__ sBl,
    int mof, int nof, int lane)
{
    const int r = lane >> 2, w = lane & 3;
#pragma unroll
    for (int ks = 0; ks < 2; ks++){
        const int kw = ks*8 + w;
        uint32_t ah[MT][4], al[MT][4], bh[NT][2], bl[NT][2];
#pragma unroll
        for (int mi = 0; mi < MT; mi++){
            int base = (mof + mi*16 + r)*SKW + kw;
            ah[mi][0] = sAh[base];     ah[mi][1] = sAh[base + 8*SKW];
            ah[mi][2] = sAh[base + 4]; ah[mi][3] = sAh[base + 8*SKW + 4];
            al[mi][0] = sAl[base];     al[mi][1] = sAl[base + 8*SKW];
            al[mi][2] = sAl[base + 4]; al[mi][3] = sAl[base + 8*SKW + 4];
        }
#pragma unroll
        for (int ni = 0; ni < NT; ni++){
            int base = (nof + ni*8 + r)*SKW + kw;
            bh[ni][0] = sBh[base]; bh[ni][1] = sBh[base + 4];
            bl[ni][0] = sBl[base]; bl[ni][1] = sBl[base + 4];
        }
#pragma unroll
        for (int mi = 0; mi < MT; mi++)
#pragma unroll
            for (int ni = 0; ni < NT; ni++){
                mma16816(acc[mi][ni], ah[mi], bh[ni]);
                mma16816(acc[mi][ni], ah[mi], bl[ni]);
                mma16816(acc[mi][ni], al[mi], bh[ni]);
            }
    }
}

__device__ __forceinline__ void store_hl(__nv_bfloat16* H, __nv_bfloat16* L,
                                         size_t off, float2 v){
    __nv_bfloat16 hx = __float2bfloat16(v.x), hy = __float2bfloat16(v.y);
    __nv_bfloat162 hp; hp.x = hx; hp.y = hy;
    __nv_bfloat162 lp;
    lp.x = __float2bfloat16(v.x - __bfloat162float(hx));
    lp.y = __float2bfloat16(v.y - __bfloat162float(hy));
    *(__nv_bfloat162*)(H + off) = hp;
    *(__nv_bfloat162*)(L + off) = lp;
}

// ============================================================
// NT GEMM, double-buffered SMEM + register prefetch.
// C[M,N] = A[M,K] @ W[N,K]^T + bias. CTA 128x128, warp tile 64x32.
// dyn smem: 2 bufs x 4 planes x GPLANE words = 81920 B
// ============================================================
template<bool OB>
__global__ __launch_bounds__(256, 1)
void gemm_proj(const float* __restrict__ A, const float* __restrict__ W,
               const float* __restrict__ bias, float* __restrict__ C,
               __nv_bfloat16* __restrict__ Ch, __nv_bfloat16* __restrict__ Cl,
               int M, int N, int K)
{
    extern __shared__ uint32_t smw[];
    const int tid = threadIdx.x, wid = tid >> 5, lane = tid & 31;
    const int wm = (wid >> 2)*64, wn = (wid & 3)*32;
    const int bm = blockIdx.y*128, bn = blockIdx.x*128;
    const int r0 = tid >> 2, s0 = tid & 3;

    float acc[4][4][4];
#pragma unroll
    for (int i = 0; i < 4; i++)
#pragma unroll
        for (int j = 0; j < 4; j++)
#pragma unroll
            for (int k = 0; k < 4; k++) acc[i][j][k] = 0.f;

    const float* pA0 = A + (size_t)(bm + r0)*K + s0*8;
    const float* pA1 = A + (size_t)(bm + r0 + 64)*K + s0*8;
    const float* pB0 = W + (size_t)(bn + r0)*K + s0*8;
    const float* pB1 = W + (size_t)(bn + r0 + 64)*K + s0*8;

    float4 a00,a01,a10,a11,b00,b01,b10,b11;
    a00 = *(const float4*)(pA0); a01 = *(const float4*)(pA0+4);
    a10 = *(const float4*)(pA1); a11 = *(const float4*)(pA1+4);
    b00 = *(const float4*)(pB0); b01 = *(const float4*)(pB0+4);
    b10 = *(const float4*)(pB1); b11 = *(const float4*)(pB1+4);

    auto store_buf = [&](uint32_t* bp){
        uint4 hh, ll;
        cvt8v(a00, a01, hh, ll);
        *(uint4*)(bp + 0*GPLANE + r0*SKW + s0*4) = hh;
        *(uint4*)(bp + 1*GPLANE + r0*SKW + s0*4) = ll;
        cvt8v(a10, a11, hh, ll);
        *(uint4*)(bp + 0*GPLANE + (r0+64)*SKW + s0*4) = hh;
        *(uint4*)(bp + 1*GPLANE + (r0+64)*SKW + s0*4) = ll;
        cvt8v(b00, b01, hh, ll);
        *(uint4*)(bp + 2*GPLANE + r0*SKW + s0*4) = hh;
        *(uint4*)(bp + 3*GPLANE + r0*SKW + s0*4) = ll;
        cvt8v(b10, b11, hh, ll);
        *(uint4*)(bp + 2*GPLANE + (r0+64)*SKW + s0*4) = hh;
        *(uint4*)(bp + 3*GPLANE + (r0+64)*SKW + s0*4) = ll;
    };
    store_buf(smw);
    __syncthreads();

    const int nch = K >> 5;
    for (int c = 0; c < nch; c++){
        uint32_t* cur = smw + (c & 1)*4*GPLANE;
        if (c + 1 < nch){
            int off = (c+1)*32;
            a00 = *(const float4*)(pA0+off); a01 = *(const float4*)(pA0+off+4);
            a10 = *(const float4*)(pA1+off); a11 = *(const float4*)(pA1+off+4);
            b00 = *(const float4*)(pB0+off); b01 = *(const float4*)(pB0+off+4);
            b10 = *(const float4*)(pB1+off); b11 = *(const float4*)(pB1+off+4);
        }
        mma_chunk<4,4>(acc, cur, cur + GPLANE, cur + 2*GPLANE, cur + 3*GPLANE, wm, wn, lane);
        if (c + 1 < nch) store_buf(smw + ((c+1) & 1)*4*GPLANE);
        __syncthreads();
    }

    const int r = lane >> 2, cl = (lane & 3)*2;
#pragma unroll
    for (int mi = 0; mi < 4; mi++){
#pragma unroll
        for (int ni = 0; ni < 4; ni++){
            int row = bm + wm + mi*16 + r;
            int col = bn + wn + ni*8 + cl;
            float2 bv = *(const float2*)(bias + col);
            float2 o0, o1;
            o0.x = acc[mi][ni][0] + bv.x; o0.y = acc[mi][ni][1] + bv.y;
            o1.x = acc[mi][ni][2] + bv.x; o1.y = acc[mi][ni][3] + bv.y;
            if (OB){
                store_hl(Ch, Cl, (size_t)row*N + col, o0);
                store_hl(Ch, Cl, (size_t)(row+8)*N + col, o1);
            } else {
                *(float2*)(C + (size_t)row*N + col)     = o0;
                *(float2*)(C + (size_t)(row+8)*N + col) = o1;
            }
        }
    }
}

// ============================================================
// scores[bh,q,k] = (Q.K)/8 masked -> raw fp32. Operands from bf16 planes.
// dyn smem: 4 planes x SCPLANE = 81920 B
// ============================================================
__global__ __launch_bounds__(256, 1)
void scores_mma(const __nv_bfloat16* __restrict__ Qh, const __nv_bfloat16* __restrict__ Ql,
                const __nv_bfloat16* __restrict__ Kh, const __nv_bfloat16* __restrict__ Kl,
                const int* __restrict__ mask, float* __restrict__ attn)
{
    extern __shared__ uint32_t smw[];
    uint32_t* sQh = smw;
    uint32_t* sQl = smw + SCPLANE;
    uint32_t* sKh = smw + 2*SCPLANE;
    uint32_t* sKl = smw + 3*SCPLANE;

    const int tid = threadIdx.x, wid = tid >> 5, lane = tid & 31;
    const int wm = (wid >> 2)*64, wn = (wid & 3)*32;
    const int bh = blockIdx.z, b = bh >> 4, h = bh & 15;
    const int bm = blockIdx.y*128, bn = blockIdx.x*128;

#pragma unroll
    for (int i = 0; i < 4; i++){
        int u = tid + i*256;                 // 1024 units of 8 bf16
        int ch = u >> 9, row = (u >> 2) & 127, s = u & 3;
        size_t gq = ((size_t)(b*SEQ + bm + row))*EMB + h*DH + ch*32 + s*8;
        size_t gk = ((size_t)(b*SEQ + bn + row))*EMB + h*DH + ch*32 + s*8;
        int wb = ch*GPLANE + row*SKW + s*4;
        *(uint4*)(sQh + wb) = *(const uint4*)(Qh + gq);
        *(uint4*)(sQl + wb) = *(const uint4*)(Ql + gq);
        *(uint4*)(sKh + wb) = *(const uint4*)(Kh + gk);
        *(uint4*)(sKl + wb) = *(const uint4*)(Kl + gk);
    }
    __syncthreads();

    float acc[4][4][4];
#pragma unroll
    for (int i = 0; i < 4; i++)
#pragma unroll
        for (int j = 0; j < 4; j++)
#pragma unroll
            for (int k = 0; k < 4; k++) acc[i][j][k] = 0.f;

#pragma unroll
    for (int ch = 0; ch < 2; ch++)
        mma_chunk<4,4>(acc, sQh + ch*GPLANE, sQl + ch*GPLANE,
                       sKh + ch*GPLANE, sKl + ch*GPLANE, wm, wn, lane);

    const int r = lane >> 2, cl = (lane & 3)*2;
    float* out = attn + (size_t)bh*SS;
#pragma unroll
    for (int mi = 0; mi < 4; mi++){
#pragma unroll
        for (int ni = 0; ni < 4; ni++){
            int row = bm + wm + mi*16 + r;
            int col = bn + wn + ni*8 + cl;
#pragma unroll
            for (int half = 0; half < 2; half++){
                int q = row + half*8;
                int2 m = *(const int2*)(mask + ((size_t)b*SEQ + q)*SEQ + col);
                float2 o;
                o.x = (m.x == 0) ? -1e9f : acc[mi][ni][half*2+0]*0.125f;
                o.y = (m.y == 0) ? -1e9f : acc[mi][ni][half*2+1]*0.125f;
                *(float2*)(out + (size_t)q*SEQ + col) = o;
            }
        }
    }
}

// ============================================================
// stats + head-average: per row compute (max, 1/sum); write avg directly.
// CTA per (b,q); thread t: head h = t>>4, 64-col segment part = t&15.
// dyn smem: 256*68*4 = 69632 B
// ============================================================
#define SM_STAT (256*68*4)

__global__ __launch_bounds__(256)
void stats_avg(const float* __restrict__ attn, float* __restrict__ avg,
               float2* __restrict__ stats)
{
    extern __shared__ float sp[];
    const int bq = blockIdx.x, b = bq >> 10, q = bq & 1023;
    const int t = threadIdx.x, h = t >> 4, part = t & 15;
    const float* row = attn + ((size_t)(b*NH + h)*SEQ + q)*SEQ + part*64;

    float4 v[16];
    float m = -3.0e38f;
#pragma unroll
    for (int i = 0; i < 16; i++){
        v[i] = ((const float4*)row)[i];
        m = fmaxf(m, fmaxf(fmaxf(v[i].x, v[i].y), fmaxf(v[i].z, v[i].w)));
    }
#pragma unroll
    for (int o = 8; o; o >>= 1) m = fmaxf(m, __shfl_xor_sync(0xffffffffu, m, o));

    float ssum = 0.f;
#pragma unroll
    for (int i = 0; i < 16; i++){
        v[i].x = __expf(v[i].x - m); v[i].y = __expf(v[i].y - m);
        v[i].z = __expf(v[i].z - m); v[i].w = __expf(v[i].w - m);
        ssum += v[i].x + v[i].y + v[i].z + v[i].w;
    }
#pragma unroll
    for (int o = 8; o; o >>= 1) ssum += __shfl_xor_sync(0xffffffffu, ssum, o);

    const float inv = 1.0f / ssum;
    if (part == 0)
        stats[(size_t)(b*NH + h)*SEQ + q] = make_float2(m, inv);

    float* slot = sp + (h*16 + part)*68;
#pragma unroll
    for (int i = 0; i < 16; i++){
        v[i].x *= inv; v[i].y *= inv; v[i].z *= inv; v[i].w *= inv;
        *(float4*)(slot + i*4) = v[i];
    }
    __syncthreads();

    const int part2 = t >> 4, j = t & 15;
    float4 a4 = make_float4(0.f, 0.f, 0.f, 0.f);
#pragma unroll
    for (int hh = 0; hh < 16; hh++){
        float4 p = *(const float4*)(sp + (hh*16 + part2)*68 + j*4);
        a4.x += p.x; a4.y += p.y; a4.z += p.z; a4.w += p.w;
    }
    a4.x *= 0.0625f; a4.y *= 0.0625f; a4.z *= 0.0625f; a4.w *= 0.0625f;
    *(float4*)(avg + ((size_t)b*SEQ + q)*SEQ + t*4) = a4;
}

// ============================================================
// ctx = softmax(P) @ V, P normalized on the fly from raw scores + stats.
// CTA 128x64 per bh, warp tile 64x16, double-buffered.
// dyn smem: 2 bufs x CTXBUF words = 61440 B
// ============================================================
__global__ __launch_bounds__(256, 1)
void ctx_mma(const float* __restrict__ attn,
             const __nv_bfloat16* __restrict__ Vth, const __nv_bfloat16* __restrict__ Vtl,
             const float2* __restrict__ stats, float* __restrict__ ctx)
{
    extern __shared__ uint32_t smw[];
    const int tid = threadIdx.x, wid = tid >> 5, lane = tid & 31;
    const int wm = (wid >> 2)*64, wn2 = (wid & 3)*16;
    const int bh = blockIdx.y, b = bh >> 4, h = bh & 15;
    const int bm = blockIdx.x*128;
    const float* Ab = attn + (size_t)bh*SS + (size_t)bm*SEQ;
    const __nv_bfloat16* BbH = Vth + ((size_t)b*EMB + h*DH)*SEQ;
    const __nv_bfloat16* BbL = Vtl + ((size_t)b*EMB + h*DH)*SEQ;

    const int ar = tid >> 2, as = tid & 3;        // A rows ar, ar+64; B row ar (0..63)
    const float2 st0 = stats[(size_t)bh*SEQ + bm + ar];
    const float2 st1 = stats[(size_t)bh*SEQ + bm + ar + 64];

    float acc[4][2][4];
#pragma unroll
    for (int i = 0; i < 4; i++)
#pragma unroll
        for (int j = 0; j < 2; j++)
#pragma unroll
            for (int k = 0; k < 4; k++) acc[i][j][k] = 0.f;

    const float* pa0 = Ab + (size_t)ar*SEQ + as*8;
    const float* pa1 = Ab + (size_t)(ar + 64)*SEQ + as*8;
    const __nv_bfloat16* pbh = BbH + (size_t)ar*SEQ + as*8;
    const __nv_bfloat16* pbl = BbL + (size_t)ar*SEQ + as*8;

    float4 ra0, ra1, ra2, ra3;
    uint4 rbh, rbl;
    ra0 = *(const float4*)(pa0); ra1 = *(const float4*)(pa0+4);
    ra2 = *(const float4*)(pa1); ra3 = *(const float4*)(pa1+4);
    rbh = *(const uint4*)(pbh);  rbl = *(const uint4*)(pbl);

    auto store_buf = [&](uint32_t* bp){
        float4 t0, t1;
        t0.x = __expf(ra0.x - st0.x)*st0.y; t0.y = __expf(ra0.y - st0.x)*st0.y;
        t0.z = __expf(ra0.z - st0.x)*st0.y; t0.w = __expf(ra0.w - st0.x)*st0.y;
        t1.x = __expf(ra1.x - st0.x)*st0.y; t1.y = __expf(ra1.y - st0.x)*st0.y;
        t1.z = __expf(ra1.z - st0.x)*st0.y; t1.w = __expf(ra1.w - st0.x)*st0.y;
        uint4 hh, ll;
        cvt8v(t0, t1, hh, ll);
        *(uint4*)(bp + 0*GPLANE + ar*SKW + as*4) = hh;
        *(uint4*)(bp + 1*GPLANE + ar*SKW + as*4) = ll;
        t0.x = __expf(ra2.x - st1.x)*st1.y; t0.y = __expf(ra2.y - st1.x)*st1.y;
        t0.z = __expf(ra2.z - st1.x)*st1.y; t0.w = __expf(ra2.w - st1.x)*st1.y;
        t1.x = __expf(ra3.x - st1.x)*st1.y; t1.y = __expf(ra3.y - st1.x)*st1.y;
        t1.z = __expf(ra3.z - st1.x)*st1.y; t1.w = __expf(ra3.w - st1.x)*st1.y;
        cvt8v(t0, t1, hh, ll);
        *(uint4*)(bp + 0*GPLANE + (ar+64)*SKW + as*4) = hh;
        *(uint4*)(bp + 1*GPLANE + (ar+64)*SKW + as*4) = ll;
        *(uint4*)(bp + 2*GPLANE + ar*SKW + as*4) = rbh;
        *(uint4*)(bp + 2*GPLANE + BPLN + ar*SKW + as*4) = rbl;
    };
    store_buf(smw);
    __syncthreads();

    for (int c = 0; c < 32; c++){
        uint32_t* cur = smw + (c & 1)*CTXBUF;
        if (c < 31){
            int off = (c+1)*32;
            ra0 = *(const float4*)(pa0+off); ra1 = *(const float4*)(pa0+off+4);
            ra2 = *(const float4*)(pa1+off); ra3 = *(const float4*)(pa1+off+4);
            rbh = *(const uint4*)(pbh+off);  rbl = *(const uint4*)(pbl+off);
        }
        mma_chunk<4,2>(acc, cur, cur + GPLANE, cur + 2*GPLANE, cur + 2*GPLANE + BPLN,
                       wm, wn2, lane);
        if (c < 31) store_buf(smw + ((c+1) & 1)*CTXBUF);
        __syncthreads();
    }

    const int r = lane >> 2, cl = (lane & 3)*2;
#pragma unroll
    for (int mi = 0; mi < 4; mi++){
#pragma unroll
        for (int ni = 0; ni < 2; ni++){
            int row = bm + wm + mi*16 + r;
            int col = wn2 + ni*8 + cl;
            float* base = ctx + ((size_t)b*SEQ + row)*EMB + h*DH + col;
            float2 o0, o1;
            o0.x = acc[mi][ni][0]; o0.y = acc[mi][ni][1];
            o1.x = acc[mi][ni][2]; o1.y = acc[mi][ni][3];
            *(float2*)(base)         = o0;
            *(float2*)(base + 8*EMB) = o1;
        }
    }
}

// ============================================================
// V transpose + hi/lo split: Vt[b][e][s] = split(V[b][s][e])
// ============================================================
__global__ void transpose_k(const float* __restrict__ V,
                            __nv_bfloat16* __restrict__ Vth,
                            __nv_bfloat16* __restrict__ Vtl)
{
    __shared__ float tile[32][33];
    const int b = blockIdx.z;
    const int e0 = blockIdx.x*32, s0 = blockIdx.y*32;
    const int tx = threadIdx.x, ty = threadIdx.y;
    const float* src = V + (size_t)b*SEQ*EMB;
#pragma unroll
    for (int i = 0; i < 32; i += 8)
        tile[ty + i][tx] = src[(size_t)(s0 + ty + i)*EMB + e0 + tx];
    __syncthreads();
#pragma unroll
    for (int i = 0; i < 32; i += 8){
        float v = tile[tx][ty + i];
        __nv_bfloat16 hb = __float2bfloat16(v);
        size_t off = ((size_t)b*EMB + e0 + ty + i)*SEQ + s0 + tx;
        Vth[off] = hb;
        Vtl[off] = __float2bfloat16(v - __bfloat162float(hb));
    }
}

// ============================================================
extern "C" void kernel_launch(void* const* d_in, const int* in_sizes, int n_in,
                              void* d_out, int out_size)
{
    const float* query = (const float*)d_in[0];
    const float* key   = (const float*)d_in[1];
    const float* value = (const float*)d_in[2];
    const int*   mask  = (const int*)  d_in[3];
    const float* Wq = (const float*)d_in[4];
    const float* bq = (const float*)d_in[5];
    const float* Wk = (const float*)d_in[6];
    const float* bk = (const float*)d_in[7];
    const float* Wv = (const float*)d_in[8];
    const float* bv = (const float*)d_in[9];
    const float* Wo = (const float*)d_in[10];
    const float* bo = (const float*)d_in[11];

    float* out      = (float*)d_out;
    float* attn_avg = out + (size_t)BATCH*SEQ*EMB;

    float *V, *CTX, *ATT;
    float2* STATS;
    __nv_bfloat16 *QH, *QL, *KH, *KL, *VTH, *VTL;
    cudaGetSymbolAddress((void**)&V,     g_V);
    cudaGetSymbolAddress((void**)&CTX,   g_ctx);
    cudaGetSymbolAddress((void**)&ATT,   g_attn);
    cudaGetSymbolAddress((void**)&STATS, g_stats);
    cudaGetSymbolAddress((void**)&QH,    g_Qh);
    cudaGetSymbolAddress((void**)&QL,    g_Ql);
    cudaGetSymbolAddress((void**)&KH,    g_Kh);
    cudaGetSymbolAddress((void**)&KL,    g_Kl);
    cudaGetSymbolAddress((void**)&VTH,   g_Vth);
    cudaGetSymbolAddress((void**)&VTL,   g_Vtl);

    const int SM_GEMMD = 2*4*GPLANE*4;   // 81920
    const int SM_SCOR  = 4*SCPLANE*4;    // 81920
    const int SM_CTXD  = 2*CTXBUF*4;     // 61440

    cudaFuncSetAttribute(gemm_proj<true>,  cudaFuncAttributeMaxDynamicSharedMemorySize, SM_GEMMD);
    cudaFuncSetAttribute(gemm_proj<false>, cudaFuncAttributeMaxDynamicSharedMemorySize, SM_GEMMD);
    cudaFuncSetAttribute(scores_mma,       cudaFuncAttributeMaxDynamicSharedMemorySize, SM_SCOR);
    cudaFuncSetAttribute(ctx_mma,          cudaFuncAttributeMaxDynamicSharedMemorySize, SM_CTXD);
    cudaFuncSetAttribute(stats_avg,        cudaFuncAttributeMaxDynamicSharedMemorySize, SM_STAT);

    const int M = BATCH*SEQ;   // 4096
    dim3 gproj(EMB/128, M/128);

    gemm_proj<true><<<gproj, 256, SM_GEMMD>>>(query, Wq, bq, nullptr, QH, QL, M, EMB, EMB);
    gemm_proj<true><<<gproj, 256, SM_GEMMD>>>(key,   Wk, bk, nullptr, KH, KL, M, EMB, EMB);
    gemm_proj<false><<<gproj, 256, SM_GEMMD>>>(value, Wv, bv, V, nullptr, nullptr, M, EMB, EMB);

    transpose_k<<<dim3(EMB/32, SEQ/32, BATCH), dim3(32, 8)>>>(V, VTH, VTL);

    scores_mma<<<dim3(SEQ/128, SEQ/128, BH), 256, SM_SCOR>>>(QH, QL, KH, KL, mask, ATT);

    stats_avg<<<BATCH*SEQ, 256, SM_STAT>>>(ATT, attn_avg, STATS);

    ctx_mma<<<dim3(SEQ/128, BH), 256, SM_CTXD>>>(ATT, VTH, VTL, STATS, CTX);

    gemm_proj<false><<<gproj, 256, SM_GEMMD>>>(CTX, Wo, bo, out, nullptr, nullptr, M, EMB, EMB);
}

// round 6
// speedup vs baseline: 1.5062x; 1.0423x over previous
#include <cuda_runtime.h>
#include <cuda_bf16.h>
#include <cstdint>
#include <cstddef>

#define SEQ 1024
#define EMB 1024
#define BATCH 4
#define NH 16
#define DH 64
#define BH (BATCH*NH)
#define SS ((size_t)SEQ*(size_t)SEQ)
#define ACT ((size_t)BATCH*SEQ*EMB)

#define SKW 20            // SMEM row stride (words): 16 data + 4 pad, conflict-free
#define GPLANE (128*SKW)  // one 128x32 bf16 plane
#define BPLN   (64*SKW)   // one 64x32 bf16 plane
#define SCPLANE (2*GPLANE)
#define CTXBUF (2*GPLANE + 2*BPLN)

typedef __nv_bfloat16 bf16;

// ---- scratch (no device allocations allowed) ----
__device__ float g_V  [ACT];
__device__ float g_attn[(size_t)BH*SEQ*SEQ];   // raw masked scores
__device__ float2 g_stats[(size_t)BH*SEQ];
// projection outputs (g_Qh/g_Ql reused for ctx planes after scores)
__device__ bf16 g_Qh[ACT], g_Ql[ACT], g_Kh[ACT], g_Kl[ACT];
__device__ bf16 g_Vth[ACT], g_Vtl[ACT];
// pre-split activation inputs
__device__ bf16 g_qih[ACT], g_qil[ACT], g_kih[ACT], g_kil[ACT], g_vih[ACT], g_vil[ACT];
// pre-split weights
__device__ bf16 g_Wqh[(size_t)EMB*EMB], g_Wql[(size_t)EMB*EMB];
__device__ bf16 g_Wkh[(size_t)EMB*EMB], g_Wkl[(size_t)EMB*EMB];
__device__ bf16 g_Wvh[(size_t)EMB*EMB], g_Wvl[(size_t)EMB*EMB];
__device__ bf16 g_Woh[(size_t)EMB*EMB], g_Wol[(size_t)EMB*EMB];

// ============================================================
__device__ __forceinline__ void mma16816(float* c, const uint32_t a[4], const uint32_t b[2]){
    asm volatile("mma.sync.aligned.m16n8k16.row.col.f32.bf16.bf16.f32 "
        "{%0,%1,%2,%3}, {%4,%5,%6,%7}, {%8,%9}, {%0,%1,%2,%3};"
        : "+f"(c[0]), "+f"(c[1]), "+f"(c[2]), "+f"(c[3])
        : "r"(a[0]), "r"(a[1]), "r"(a[2]), "r"(a[3]), "r"(b[0]), "r"(b[1]));
}

__device__ __forceinline__ void cvt8v(float4 x0, float4 x1, uint4& h, uint4& l){
    float x[8] = {x0.x,x0.y,x0.z,x0.w,x1.x,x1.y,x1.z,x1.w};
    uint32_t hw[8], lw[8];
#pragma unroll
    for (int j = 0; j < 8; j++){
        bf16 hb = __float2bfloat16(x[j]);
        float hf = __bfloat162float(hb);
        bf16 lb = __float2bfloat16(x[j] - hf);
        hw[j] = (uint32_t)__bfloat16_as_ushort(hb);
        lw[j] = (uint32_t)__bfloat16_as_ushort(lb);
    }
    h.x = hw[0]|(hw[1]<<16); h.y = hw[2]|(hw[3]<<16);
    h.z = hw[4]|(hw[5]<<16); h.w = hw[6]|(hw[7]<<16);
    l.x = lw[0]|(lw[1]<<16); l.y = lw[2]|(lw[3]<<16);
    l.z = lw[4]|(lw[5]<<16); l.w = lw[6]|(lw[7]<<16);
}

template<int MT, int NT>
__device__ __forceinline__ void mma_chunk(float acc[MT][NT][4],
    const uint32_t* __restrict__ sAh, const uint32_t* __restrict__ sAl,
    const uint32_t* __restrict__ sBh, const uint32_t* __restrict__ sBl,
    int mof, int nof, int lane)
{
    const int r = lane >> 2, w = lane & 3;
#pragma unroll
    for (int ks = 0; ks < 2; ks++){
        const int kw = ks*8 + w;
        uint32_t ah[MT][4], al[MT][4], bh[NT][2], bl[NT][2];
#pragma unroll
        for (int mi = 0; mi < MT; mi++){
            int base = (mof + mi*16 + r)*SKW + kw;
            ah[mi][0] = sAh[base];     ah[mi][1] = sAh[base + 8*SKW];
            ah[mi][2] = sAh[base + 4]; ah[mi][3] = sAh[base + 8*SKW + 4];
            al[mi][0] = sAl[base];     al[mi][1] = sAl[base + 8*SKW];
            al[mi][2] = sAl[base + 4]; al[mi][3] = sAl[base + 8*SKW + 4];
        }
#pragma unroll
        for (int ni = 0; ni < NT; ni++){
            int base = (nof + ni*8 + r)*SKW + kw;
            bh[ni][0] = sBh[base]; bh[ni][1] = sBh[base + 4];
            bl[ni][0] = sBl[base]; bl[ni][1] = sBl[base + 4];
        }
#pragma unroll
        for (int mi = 0; mi < MT; mi++)
#pragma unroll
            for (int ni = 0; ni < NT; ni++){
                mma16816(acc[mi][ni], ah[mi], bh[ni]);
                mma16816(acc[mi][ni], ah[mi], bl[ni]);
                mma16816(acc[mi][ni], al[mi], bh[ni]);
            }
    }
}

__device__ __forceinline__ void store_hl(bf16* H, bf16* L, size_t off, float2 v){
    bf16 hx = __float2bfloat16(v.x), hy = __float2bfloat16(v.y);
    __nv_bfloat162 hp; hp.x = hx; hp.y = hy;
    __nv_bfloat162 lp;
    lp.x = __float2bfloat16(v.x - __bfloat162float(hx));
    lp.y = __float2bfloat16(v.y - __bfloat162float(hy));
    *(__nv_bfloat162*)(H + off) = hp;
    *(__nv_bfloat162*)(L + off) = lp;
}

// ============================================================
// fp32 -> bf16 hi/lo plane split (8 elems per thread)
// ============================================================
__global__ __launch_bounds__(256)
void split_hl(const float* __restrict__ src, bf16* __restrict__ H,
              bf16* __restrict__ L, int n8)
{
    int i = blockIdx.x*blockDim.x + threadIdx.x;
    if (i >= n8) return;
    const float* p = src + (size_t)i*8;
    float4 a = *(const float4*)p, b = *(const float4*)(p+4);
    uint4 h, l;
    cvt8v(a, b, h, l);
    *(uint4*)(H + (size_t)i*8) = h;
    *(uint4*)(L + (size_t)i*8) = l;
}

// ============================================================
// plane-input NT GEMM, double-buffered: C = A @ W^T + bias
// A,W given as bf16 hi/lo planes (row-major, ld=K).
// dyn smem: 2 x 4 x GPLANE x 4B = 81920
// ============================================================
template<bool OB>
__global__ __launch_bounds__(256, 1)
void gemm_plane(const bf16* __restrict__ Ah, const bf16* __restrict__ Al,
                const bf16* __restrict__ Wh, const bf16* __restrict__ Wl,
                const float* __restrict__ bias, float* __restrict__ C,
                bf16* __restrict__ Ch, bf16* __restrict__ Cl,
                int M, int N, int K)
{
    extern __shared__ uint32_t smw[];
    const int tid = threadIdx.x, wid = tid >> 5, lane = tid & 31;
    const int wm = (wid >> 2)*64, wn = (wid & 3)*32;
    const int bm = blockIdx.y*128, bn = blockIdx.x*128;
    const int r0 = tid >> 2, s0 = tid & 3;

    float acc[4][4][4];
#pragma unroll
    for (int i = 0; i < 4; i++)
#pragma unroll
        for (int j = 0; j < 4; j++)
#pragma unroll
            for (int k = 0; k < 4; k++) acc[i][j][k] = 0.f;

    const bf16* pAh0 = Ah + (size_t)(bm + r0)*K + s0*8;
    const bf16* pAh1 = Ah + (size_t)(bm + r0 + 64)*K + s0*8;
    const bf16* pAl0 = Al + (size_t)(bm + r0)*K + s0*8;
    const bf16* pAl1 = Al + (size_t)(bm + r0 + 64)*K + s0*8;
    const bf16* pWh0 = Wh + (size_t)(bn + r0)*K + s0*8;
    const bf16* pWh1 = Wh + (size_t)(bn + r0 + 64)*K + s0*8;
    const bf16* pWl0 = Wl + (size_t)(bn + r0)*K + s0*8;
    const bf16* pWl1 = Wl + (size_t)(bn + r0 + 64)*K + s0*8;

    uint4 rah0, rah1, ral0, ral1, rbh0, rbh1, rbl0, rbl1;
    rah0 = *(const uint4*)(pAh0); rah1 = *(const uint4*)(pAh1);
    ral0 = *(const uint4*)(pAl0); ral1 = *(const uint4*)(pAl1);
    rbh0 = *(const uint4*)(pWh0); rbh1 = *(const uint4*)(pWh1);
    rbl0 = *(const uint4*)(pWl0); rbl1 = *(const uint4*)(pWl1);

    auto store_buf = [&](uint32_t* bp){
        int wb0 = r0*SKW + s0*4, wb1 = (r0+64)*SKW + s0*4;
        *(uint4*)(bp + 0*GPLANE + wb0) = rah0;
        *(uint4*)(bp + 0*GPLANE + wb1) = rah1;
        *(uint4*)(bp + 1*GPLANE + wb0) = ral0;
        *(uint4*)(bp + 1*GPLANE + wb1) = ral1;
        *(uint4*)(bp + 2*GPLANE + wb0) = rbh0;
        *(uint4*)(bp + 2*GPLANE + wb1) = rbh1;
        *(uint4*)(bp + 3*GPLANE + wb0) = rbl0;
        *(uint4*)(bp + 3*GPLANE + wb1) = rbl1;
    };
    store_buf(smw);
    __syncthreads();

    const int nch = K >> 5;
    for (int c = 0; c < nch; c++){
        uint32_t* cur = smw + (c & 1)*4*GPLANE;
        if (c + 1 < nch){
            int off = (c+1)*32;
            rah0 = *(const uint4*)(pAh0+off); rah1 = *(const uint4*)(pAh1+off);
            ral0 = *(const uint4*)(pAl0+off); ral1 = *(const uint4*)(pAl1+off);
            rbh0 = *(const uint4*)(pWh0+off); rbh1 = *(const uint4*)(pWh1+off);
            rbl0 = *(const uint4*)(pWl0+off); rbl1 = *(const uint4*)(pWl1+off);
        }
        mma_chunk<4,4>(acc, cur, cur + GPLANE, cur + 2*GPLANE, cur + 3*GPLANE, wm, wn, lane);
        if (c + 1 < nch) store_buf(smw + ((c+1) & 1)*4*GPLANE);
        __syncthreads();
    }

    const int r = lane >> 2, cl = (lane & 3)*2;
#pragma unroll
    for (int mi = 0; mi < 4; mi++){
#pragma unroll
        for (int ni = 0; ni < 4; ni++){
            int row = bm + wm + mi*16 + r;
            int col = bn + wn + ni*8 + cl;
            float2 bv = *(const float2*)(bias + col);
            float2 o0, o1;
            o0.x = acc[mi][ni][0] + bv.x; o0.y = acc[mi][ni][1] + bv.y;
            o1.x = acc[mi][ni][2] + bv.x; o1.y = acc[mi][ni][3] + bv.y;
            if (OB){
                store_hl(Ch, Cl, (size_t)row*N + col, o0);
                store_hl(Ch, Cl, (size_t)(row+8)*N + col, o1);
            } else {
                *(float2*)(C + (size_t)row*N + col)     = o0;
                *(float2*)(C + (size_t)(row+8)*N + col) = o1;
            }
        }
    }
}

// ============================================================
// scores: raw masked fp32 (unchanged from R5)
// ============================================================
__global__ __launch_bounds__(256, 1)
void scores_mma(const bf16* __restrict__ Qh, const bf16* __restrict__ Ql,
                const bf16* __restrict__ Kh, const bf16* __restrict__ Kl,
                const int* __restrict__ mask, float* __restrict__ attn)
{
    extern __shared__ uint32_t smw[];
    uint32_t* sQh = smw;
    uint32_t* sQl = smw + SCPLANE;
    uint32_t* sKh = smw + 2*SCPLANE;
    uint32_t* sKl = smw + 3*SCPLANE;

    const int tid = threadIdx.x, wid = tid >> 5, lane = tid & 31;
    const int wm = (wid >> 2)*64, wn = (wid & 3)*32;
    const int bh = blockIdx.z, b = bh >> 4, h = bh & 15;
    const int bm = blockIdx.y*128, bn = blockIdx.x*128;

#pragma unroll
    for (int i = 0; i < 4; i++){
        int u = tid + i*256;
        int ch = u >> 9, row = (u >> 2) & 127, s = u & 3;
        size_t gq = ((size_t)(b*SEQ + bm + row))*EMB + h*DH + ch*32 + s*8;
        size_t gk = ((size_t)(b*SEQ + bn + row))*EMB + h*DH + ch*32 + s*8;
        int wb = ch*GPLANE + row*SKW + s*4;
        *(uint4*)(sQh + wb) = *(const uint4*)(Qh + gq);
        *(uint4*)(sQl + wb) = *(const uint4*)(Ql + gq);
        *(uint4*)(sKh + wb) = *(const uint4*)(Kh + gk);
        *(uint4*)(sKl + wb) = *(const uint4*)(Kl + gk);
    }
    __syncthreads();

    float acc[4][4][4];
#pragma unroll
    for (int i = 0; i < 4; i++)
#pragma unroll
        for (int j = 0; j < 4; j++)
#pragma unroll
            for (int k = 0; k < 4; k++) acc[i][j][k] = 0.f;

#pragma unroll
    for (int ch = 0; ch < 2; ch++)
        mma_chunk<4,4>(acc, sQh + ch*GPLANE, sQl + ch*GPLANE,
                       sKh + ch*GPLANE, sKl + ch*GPLANE, wm, wn, lane);

    const int r = lane >> 2, cl = (lane & 3)*2;
    float* out = attn + (size_t)bh*SS;
#pragma unroll
    for (int mi = 0; mi < 4; mi++){
#pragma unroll
        for (int ni = 0; ni < 4; ni++){
            int row = bm + wm + mi*16 + r;
            int col = bn + wn + ni*8 + cl;
#pragma unroll
            for (int half = 0; half < 2; half++){
                int q = row + half*8;
                int2 m = *(const int2*)(mask + ((size_t)b*SEQ + q)*SEQ + col);
                float2 o;
                o.x = (m.x == 0) ? -1e9f : acc[mi][ni][half*2+0]*0.125f;
                o.y = (m.y == 0) ? -1e9f : acc[mi][ni][half*2+1]*0.125f;
                *(float2*)(out + (size_t)q*SEQ + col) = o;
            }
        }
    }
}

// ============================================================
// stats + head-average (unchanged from R5)
// ============================================================
#define SM_STAT (256*68*4)

__global__ __launch_bounds__(256)
void stats_avg(const float* __restrict__ attn, float* __restrict__ avg,
               float2* __restrict__ stats)
{
    extern __shared__ float sp[];
    const int bq = blockIdx.x, b = bq >> 10, q = bq & 1023;
    const int t = threadIdx.x, h = t >> 4, part = t & 15;
    const float* row = attn + ((size_t)(b*NH + h)*SEQ + q)*SEQ + part*64;

    float4 v[16];
    float m = -3.0e38f;
#pragma unroll
    for (int i = 0; i < 16; i++){
        v[i] = ((const float4*)row)[i];
        m = fmaxf(m, fmaxf(fmaxf(v[i].x, v[i].y), fmaxf(v[i].z, v[i].w)));
    }
#pragma unroll
    for (int o = 8; o; o >>= 1) m = fmaxf(m, __shfl_xor_sync(0xffffffffu, m, o));

    float ssum = 0.f;
#pragma unroll
    for (int i = 0; i < 16; i++){
        v[i].x = __expf(v[i].x - m); v[i].y = __expf(v[i].y - m);
        v[i].z = __expf(v[i].z - m); v[i].w = __expf(v[i].w - m);
        ssum += v[i].x + v[i].y + v[i].z + v[i].w;
    }
#pragma unroll
    for (int o = 8; o; o >>= 1) ssum += __shfl_xor_sync(0xffffffffu, ssum, o);

    const float inv = 1.0f / ssum;
    if (part == 0)
        stats[(size_t)(b*NH + h)*SEQ + q] = make_float2(m, inv);

    float* slot = sp + (h*16 + part)*68;
#pragma unroll
    for (int i = 0; i < 16; i++){
        v[i].x *= inv; v[i].y *= inv; v[i].z *= inv; v[i].w *= inv;
        *(float4*)(slot + i*4) = v[i];
    }
    __syncthreads();

    const int part2 = t >> 4, j = t & 15;
    float4 a4 = make_float4(0.f, 0.f, 0.f, 0.f);
#pragma unroll
    for (int hh = 0; hh < 16; hh++){
        float4 p = *(const float4*)(sp + (hh*16 + part2)*68 + j*4);
        a4.x += p.x; a4.y += p.y; a4.z += p.z; a4.w += p.w;
    }
    a4.x *= 0.0625f; a4.y *= 0.0625f; a4.z *= 0.0625f; a4.w *= 0.0625f;
    *(float4*)(avg + ((size_t)b*SEQ + q)*SEQ + t*4) = a4;
}

// ============================================================
// ctx = softmax(P) @ V; epilogue writes ctx as bf16 hi/lo planes
// ============================================================
__global__ __launch_bounds__(256, 1)
void ctx_mma(const float* __restrict__ attn,
             const bf16* __restrict__ Vth, const bf16* __restrict__ Vtl,
             const float2* __restrict__ stats,
             bf16* __restrict__ Ch, bf16* __restrict__ Cl)
{
    extern __shared__ uint32_t smw[];
    const int tid = threadIdx.x, wid = tid >> 5, lane = tid & 31;
    const int wm = (wid >> 2)*64, wn2 = (wid & 3)*16;
    const int bh = blockIdx.y, b = bh >> 4, h = bh & 15;
    const int bm = blockIdx.x*128;
    const float* Ab = attn + (size_t)bh*SS + (size_t)bm*SEQ;
    const bf16* BbH = Vth + ((size_t)b*EMB + h*DH)*SEQ;
    const bf16* BbL = Vtl + ((size_t)b*EMB + h*DH)*SEQ;

    const int ar = tid >> 2, as = tid & 3;
    const float2 st0 = stats[(size_t)bh*SEQ + bm + ar];
    const float2 st1 = stats[(size_t)bh*SEQ + bm + ar + 64];

    float acc[4][2][4];
#pragma unroll
    for (int i = 0; i < 4; i++)
#pragma unroll
        for (int j = 0; j < 2; j++)
#pragma unroll
            for (int k = 0; k < 4; k++) acc[i][j][k] = 0.f;

    const float* pa0 = Ab + (size_t)ar*SEQ + as*8;
    const float* pa1 = Ab + (size_t)(ar + 64)*SEQ + as*8;
    const bf16* pbh = BbH + (size_t)ar*SEQ + as*8;
    const bf16* pbl = BbL + (size_t)ar*SEQ + as*8;

    float4 ra0, ra1, ra2, ra3;
    uint4 rbh, rbl;
    ra0 = *(const float4*)(pa0); ra1 = *(const float4*)(pa0+4);
    ra2 = *(const float4*)(pa1); ra3 = *(const float4*)(pa1+4);
    rbh = *(const uint4*)(pbh);  rbl = *(const uint4*)(pbl);

    auto store_buf = [&](uint32_t* bp){
        float4 t0, t1;
        t0.x = __expf(ra0.x - st0.x)*st0.y; t0.y = __expf(ra0.y - st0.x)*st0.y;
        t0.z = __expf(ra0.z - st0.x)*st0.y; t0.w = __expf(ra0.w - st0.x)*st0.y;
        t1.x = __expf(ra1.x - st0.x)*st0.y; t1.y = __expf(ra1.y - st0.x)*st0.y;
        t1.z = __expf(ra1.z - st0.x)*st0.y; t1.w = __expf(ra1.w - st0.x)*st0.y;
        uint4 hh, ll;
        cvt8v(t0, t1, hh, ll);
        *(uint4*)(bp + 0*GPLANE + ar*SKW + as*4) = hh;
        *(uint4*)(bp + 1*GPLANE + ar*SKW + as*4) = ll;
        t0.x = __expf(ra2.x - st1.x)*st1.y; t0.y = __expf(ra2.y - st1.x)*st1.y;
        t0.z = __expf(ra2.z - st1.x)*st1.y; t0.w = __expf(ra2.w - st1.x)*st1.y;
        t1.x = __expf(ra3.x - st1.x)*st1.y; t1.y = __expf(ra3.y - st1.x)*st1.y;
        t1.z = __expf(ra3.z - st1.x)*st1.y; t1.w = __expf(ra3.w - st1.x)*st1.y;
        cvt8v(t0, t1, hh, ll);
        *(uint4*)(bp + 0*GPLANE + (ar+64)*SKW + as*4) = hh;
        *(uint4*)(bp + 1*GPLANE + (ar+64)*SKW + as*4) = ll;
        *(uint4*)(bp + 2*GPLANE + ar*SKW + as*4) = rbh;
        *(uint4*)(bp + 2*GPLANE + BPLN + ar*SKW + as*4) = rbl;
    };
    store_buf(smw);
    __syncthreads();

    for (int c = 0; c < 32; c++){
        uint32_t* cur = smw + (c & 1)*CTXBUF;
        if (c < 31){
            int off = (c+1)*32;
            ra0 = *(const float4*)(pa0+off); ra1 = *(const float4*)(pa0+off+4);
            ra2 = *(const float4*)(pa1+off); ra3 = *(const float4*)(pa1+off+4);
            rbh = *(const uint4*)(pbh+off);  rbl = *(const uint4*)(pbl+off);
        }
        mma_chunk<4,2>(acc, cur, cur + GPLANE, cur + 2*GPLANE, cur + 2*GPLANE + BPLN,
                       wm, wn2, lane);
        if (c < 31) store_buf(smw + ((c+1) & 1)*CTXBUF);
        __syncthreads();
    }

    const int r = lane >> 2, cl = (lane & 3)*2;
#pragma unroll
    for (int mi = 0; mi < 4; mi++){
#pragma unroll
        for (int ni = 0; ni < 2; ni++){
            int row = bm + wm + mi*16 + r;
            int col = h*DH + wn2 + ni*8 + cl;
            float2 o0, o1;
            o0.x = acc[mi][ni][0]; o0.y = acc[mi][ni][1];
            o1.x = acc[mi][ni][2]; o1.y = acc[mi][ni][3];
            store_hl(Ch, Cl, ((size_t)b*SEQ + row)*EMB + col, o0);
            store_hl(Ch, Cl, ((size_t)b*SEQ + row + 8)*EMB + col, o1);
        }
    }
}

// ============================================================
// V transpose + hi/lo split (unchanged)
// ============================================================
__global__ void transpose_k(const float* __restrict__ V,
                            bf16* __restrict__ Vth, bf16* __restrict__ Vtl)
{
    __shared__ float tile[32][33];
    const int b = blockIdx.z;
    const int e0 = blockIdx.x*32, s0 = blockIdx.y*32;
    const int tx = threadIdx.x, ty = threadIdx.y;
    const float* src = V + (size_t)b*SEQ*EMB;
#pragma unroll
    for (int i = 0; i < 32; i += 8)
        tile[ty + i][tx] = src[(size_t)(s0 + ty + i)*EMB + e0 + tx];
    __syncthreads();
#pragma unroll
    for (int i = 0; i < 32; i += 8){
        float v = tile[tx][ty + i];
        bf16 hb = __float2bfloat16(v);
        size_t off = ((size_t)b*EMB + e0 + ty + i)*SEQ + s0 + tx;
        Vth[off] = hb;
        Vtl[off] = __float2bfloat16(v - __bfloat162float(hb));
    }
}

// ============================================================
extern "C" void kernel_launch(void* const* d_in, const int* in_sizes, int n_in,
                              void* d_out, int out_size)
{
    const float* query = (const float*)d_in[0];
    const float* key   = (const float*)d_in[1];
    const float* value = (const float*)d_in[2];
    const int*   mask  = (const int*)  d_in[3];
    const float* Wq = (const float*)d_in[4];
    const float* bq = (const float*)d_in[5];
    const float* Wk = (const float*)d_in[6];
    const float* bk = (const float*)d_in[7];
    const float* Wv = (const float*)d_in[8];
    const float* bv = (const float*)d_in[9];
    const float* Wo = (const float*)d_in[10];
    const float* bo = (const float*)d_in[11];

    float* out      = (float*)d_out;
    float* attn_avg = out + ACT;

    float *V, *ATT; float2* STATS;
    bf16 *QH, *QL, *KH, *KL, *VTH, *VTL;
    bf16 *QIH, *QIL, *KIH, *KIL, *VIH, *VIL;
    bf16 *WQH, *WQL, *WKH, *WKL, *WVH, *WVL, *WOH, *WOL;
    cudaGetSymbolAddress((void**)&V,     g_V);
    cudaGetSymbolAddress((void**)&ATT,   g_attn);
    cudaGetSymbolAddress((void**)&STATS, g_stats);
    cudaGetSymbolAddress((void**)&QH,  g_Qh);  cudaGetSymbolAddress((void**)&QL,  g_Ql);
    cudaGetSymbolAddress((void**)&KH,  g_Kh);  cudaGetSymbolAddress((void**)&KL,  g_Kl);
    cudaGetSymbolAddress((void**)&VTH, g_Vth); cudaGetSymbolAddress((void**)&VTL, g_Vtl);
    cudaGetSymbolAddress((void**)&QIH, g_qih); cudaGetSymbolAddress((void**)&QIL, g_qil);
    cudaGetSymbolAddress((void**)&KIH, g_kih); cudaGetSymbolAddress((void**)&KIL, g_kil);
    cudaGetSymbolAddress((void**)&VIH, g_vih); cudaGetSymbolAddress((void**)&VIL, g_vil);
    cudaGetSymbolAddress((void**)&WQH, g_Wqh); cudaGetSymbolAddress((void**)&WQL, g_Wql);
    cudaGetSymbolAddress((void**)&WKH, g_Wkh); cudaGetSymbolAddress((void**)&WKL, g_Wkl);
    cudaGetSymbolAddress((void**)&WVH, g_Wvh); cudaGetSymbolAddress((void**)&WVL, g_Wvl);
    cudaGetSymbolAddress((void**)&WOH, g_Woh); cudaGetSymbolAddress((void**)&WOL, g_Wol);

    const int SM_GEMMD = 2*4*GPLANE*4;   // 81920
    const int SM_SCOR  = 4*SCPLANE*4;    // 81920
    const int SM_CTXD  = 2*CTXBUF*4;     // 61440

    cudaFuncSetAttribute(gemm_plane<true>,  cudaFuncAttributeMaxDynamicSharedMemorySize, SM_GEMMD);
    cudaFuncSetAttribute(gemm_plane<false>, cudaFuncAttributeMaxDynamicSharedMemorySize, SM_GEMMD);
    cudaFuncSetAttribute(scores_mma, cudaFuncAttributeMaxDynamicSharedMemorySize, SM_SCOR);
    cudaFuncSetAttribute(ctx_mma,    cudaFuncAttributeMaxDynamicSharedMemorySize, SM_CTXD);
    cudaFuncSetAttribute(stats_avg,  cudaFuncAttributeMaxDynamicSharedMemorySize, SM_STAT);

    const int M = BATCH*SEQ;   // 4096
    const int nact8 = (int)(ACT/8), nw8 = (int)((size_t)EMB*EMB/8);

    split_hl<<<(nact8+255)/256, 256>>>(query, QIH, QIL, nact8);
    split_hl<<<(nact8+255)/256, 256>>>(key,   KIH, KIL, nact8);
    split_hl<<<(nact8+255)/256, 256>>>(value, VIH, VIL, nact8);
    split_hl<<<(nw8+255)/256, 256>>>(Wq, WQH, WQL, nw8);
    split_hl<<<(nw8+255)/256, 256>>>(Wk, WKH, WKL, nw8);
    split_hl<<<(nw8+255)/256, 256>>>(Wv, WVH, WVL, nw8);
    split_hl<<<(nw8+255)/256, 256>>>(Wo, WOH, WOL, nw8);

    dim3 gproj(EMB/128, M/128);
    gemm_plane<true><<<gproj, 256, SM_GEMMD>>>(QIH, QIL, WQH, WQL, bq, nullptr, QH, QL, M, EMB, EMB);
    gemm_plane<true><<<gproj, 256, SM_GEMMD>>>(KIH, KIL, WKH, WKL, bk, nullptr, KH, KL, M, EMB, EMB);
    gemm_plane<false><<<gproj, 256, SM_GEMMD>>>(VIH, VIL, WVH, WVL, bv, V, nullptr, nullptr, M, EMB, EMB);

    transpose_k<<<dim3(EMB/32, SEQ/32, BATCH), dim3(32, 8)>>>(V, VTH, VTL);

    scores_mma<<<dim3(SEQ/128, SEQ/128, BH), 256, SM_SCOR>>>(QH, QL, KH, KL, mask, ATT);

    stats_avg<<<BATCH*SEQ, 256, SM_STAT>>>(ATT, attn_avg, STATS);

    // ctx planes reuse Q-plane buffers (Q dead after scores_mma)
    ctx_mma<<<dim3(SEQ/128, BH), 256, SM_CTXD>>>(ATT, VTH, VTL, STATS, QH, QL);

    gemm_plane<false><<<gproj, 256, SM_GEMMD>>>(QH, QL, WOH, WOL, bo, out, nullptr, nullptr, M, EMB, EMB);
}

// round 7
// speedup vs baseline: 1.5620x; 1.0371x over previous
#include <cuda_runtime.h>
#include <cuda_bf16.h>
#include <cstdint>
#include <cstddef>

#define SEQ 1024
#define EMB 1024
#define BATCH 4
#define NH 16
#define DH 64
#define BH (BATCH*NH)
#define SS ((size_t)SEQ*(size_t)SEQ)
#define ACT ((size_t)BATCH*SEQ*EMB)
#define EE  ((size_t)EMB*EMB)

#define SKW 20            // SMEM row stride (words): 16 data + 4 pad
#define GPLANE (128*SKW)  // one 128x32 bf16 plane (words)
#define BPLN   (64*SKW)
#define SCPLANE (2*GPLANE)
#define CTXBUF (2*GPLANE + 2*BPLN)

typedef __nv_bfloat16 bf16;

// ---- scratch: hi plane at [0], lo plane at [size] ----
__device__ float g_V  [ACT];
__device__ float g_attn[(size_t)BH*SEQ*SEQ];
__device__ float2 g_stats[(size_t)BH*SEQ];
__device__ bf16 g_qi[2*ACT], g_ki[2*ACT], g_vi[2*ACT];       // split inputs
__device__ bf16 g_Wq2[2*EE], g_Wk2[2*EE], g_Wv2[2*EE], g_Wo2[2*EE];
__device__ bf16 g_Q2[2*ACT], g_K2[2*ACT];                    // proj outputs (g_Q2 reused for ctx)
__device__ bf16 g_Vt2[2*ACT];

// ============================================================
__device__ __forceinline__ void mma16816(float* c, const uint32_t a[4], const uint32_t b[2]){
    asm volatile("mma.sync.aligned.m16n8k16.row.col.f32.bf16.bf16.f32 "
        "{%0,%1,%2,%3}, {%4,%5,%6,%7}, {%8,%9}, {%0,%1,%2,%3};"
        : "+f"(c[0]), "+f"(c[1]), "+f"(c[2]), "+f"(c[3])
        : "r"(a[0]), "r"(a[1]), "r"(a[2]), "r"(a[3]), "r"(b[0]), "r"(b[1]));
}

__device__ __forceinline__ void cvt8v(float4 x0, float4 x1, uint4& h, uint4& l){
    float x[8] = {x0.x,x0.y,x0.z,x0.w,x1.x,x1.y,x1.z,x1.w};
    uint32_t hw[8], lw[8];
#pragma unroll
    for (int j = 0; j < 8; j++){
        bf16 hb = __float2bfloat16(x[j]);
        float hf = __bfloat162float(hb);
        bf16 lb = __float2bfloat16(x[j] - hf);
        hw[j] = (uint32_t)__bfloat16_as_ushort(hb);
        lw[j] = (uint32_t)__bfloat16_as_ushort(lb);
    }
    h.x = hw[0]|(hw[1]<<16); h.y = hw[2]|(hw[3]<<16);
    h.z = hw[4]|(hw[5]<<16); h.w = hw[6]|(hw[7]<<16);
    l.x = lw[0]|(lw[1]<<16); l.y = lw[2]|(lw[3]<<16);
    l.z = lw[4]|(lw[5]<<16); l.w = lw[6]|(lw[7]<<16);
}

// register-lean bf16x3 chunk: B-frags hoisted per ks, A-frags per mi.
// Per-acc MMA order identical to prior rounds (hh, hl, lh per ks).
template<int MT, int NT>
__device__ __forceinline__ void mma_chunk(float acc[MT][NT][4],
    const uint32_t* __restrict__ sAh, const uint32_t* __restrict__ sAl,
    const uint32_t* __restrict__ sBh, const uint32_t* __restrict__ sBl,
    int mof, int nof, int lane)
{
    const int r = lane >> 2, w = lane & 3;
#pragma unroll
    for (int ks = 0; ks < 2; ks++){
        const int kw = ks*8 + w;
        uint32_t bh[NT][2], bl[NT][2];
#pragma unroll
        for (int ni = 0; ni < NT; ni++){
            int base = (nof + ni*8 + r)*SKW + kw;
            bh[ni][0] = sBh[base]; bh[ni][1] = sBh[base + 4];
            bl[ni][0] = sBl[base]; bl[ni][1] = sBl[base + 4];
        }
#pragma unroll
        for (int mi = 0; mi < MT; mi++){
            int base = (mof + mi*16 + r)*SKW + kw;
            uint32_t ah[4], al[4];
            ah[0] = sAh[base];     ah[1] = sAh[base + 8*SKW];
            ah[2] = sAh[base + 4]; ah[3] = sAh[base + 8*SKW + 4];
            al[0] = sAl[base];     al[1] = sAl[base + 8*SKW];
            al[2] = sAl[base + 4]; al[3] = sAl[base + 8*SKW + 4];
#pragma unroll
            for (int ni = 0; ni < NT; ni++){
                mma16816(acc[mi][ni], ah, bh[ni]);
                mma16816(acc[mi][ni], ah, bl[ni]);
                mma16816(acc[mi][ni], al, bh[ni]);
            }
        }
    }
}

__device__ __forceinline__ void store_hl(bf16* H, bf16* L, size_t off, float2 v){
    bf16 hx = __float2bfloat16(v.x), hy = __float2bfloat16(v.y);
    __nv_bfloat162 hp; hp.x = hx; hp.y = hy;
    __nv_bfloat162 lp;
    lp.x = __float2bfloat16(v.x - __bfloat162float(hx));
    lp.y = __float2bfloat16(v.y - __bfloat162float(hy));
    *(__nv_bfloat162*)(H + off) = hp;
    *(__nv_bfloat162*)(L + off) = lp;
}

__device__ __forceinline__ void cp16(uint32_t dst, const void* src){
    asm volatile("cp.async.cg.shared.global [%0], [%1], 16;" :: "r"(dst), "l"(src));
}
#define CP_COMMIT() asm volatile("cp.async.commit_group;" ::: "memory")
#define CP_WAIT0()  asm volatile("cp.async.wait_group 0;" ::: "memory")

// ============================================================
// split kernels: grid.y selects tensor
// ============================================================
__global__ __launch_bounds__(256)
void split_act(const float* __restrict__ q, const float* __restrict__ k,
               const float* __restrict__ v,
               bf16* __restrict__ qo, bf16* __restrict__ ko, bf16* __restrict__ vo,
               int n8)
{
    int i = blockIdx.x*blockDim.x + threadIdx.x;
    if (i >= n8) return;
    const float* src = (blockIdx.y == 0) ? q : (blockIdx.y == 1) ? k : v;
    bf16* H = (blockIdx.y == 0) ? qo : (blockIdx.y == 1) ? ko : vo;
    const float* p = src + (size_t)i*8;
    uint4 h, l;
    cvt8v(*(const float4*)p, *(const float4*)(p+4), h, l);
    *(uint4*)(H + (size_t)i*8) = h;
    *(uint4*)(H + ACT + (size_t)i*8) = l;
}

__global__ __launch_bounds__(256)
void split_w(const float* __restrict__ wq, const float* __restrict__ wk,
             const float* __restrict__ wv, const float* __restrict__ wo,
             bf16* __restrict__ oq, bf16* __restrict__ ok,
             bf16* __restrict__ ov, bf16* __restrict__ oo, int n8)
{
    int i = blockIdx.x*blockDim.x + threadIdx.x;
    if (i >= n8) return;
    const float* src = (blockIdx.y == 0) ? wq : (blockIdx.y == 1) ? wk :
                       (blockIdx.y == 2) ? wv : wo;
    bf16* H = (blockIdx.y == 0) ? oq : (blockIdx.y == 1) ? ok :
              (blockIdx.y == 2) ? ov : oo;
    const float* p = src + (size_t)i*8;
    uint4 h, l;
    cvt8v(*(const float4*)p, *(const float4*)(p+4), h, l);
    *(uint4*)(H + (size_t)i*8) = h;
    *(uint4*)(H + EE + (size_t)i*8) = l;
}

// ============================================================
// NT GEMM v2: cp.async double-buffered, 2 CTAs/SM.
// A planes: hi at A, lo at A+ACT. W planes: hi at W, lo at W+EE.
// dyn smem: 2 bufs x 4 planes x GPLANE x 4B = 81920
// ============================================================
template<bool OB>
__global__ __launch_bounds__(256, 2)
void gemm_plane(const bf16* __restrict__ A, const bf16* __restrict__ W,
                const float* __restrict__ bias, float* __restrict__ C,
                bf16* __restrict__ Ch,
                int M, int N, int K)
{
    extern __shared__ __align__(16) uint32_t smw[];
    const uint32_t sb = (uint32_t)__cvta_generic_to_shared(smw);
    const int tid = threadIdx.x, wid = tid >> 5, lane = tid & 31;
    const int wm = (wid >> 2)*64, wn = (wid & 3)*32;
    const int bm = blockIdx.y*128, bn = blockIdx.x*128;
    const int r0 = tid >> 2, s0 = tid & 3;

    float acc[4][4][4];
#pragma unroll
    for (int i = 0; i < 4; i++)
#pragma unroll
        for (int j = 0; j < 4; j++)
#pragma unroll
            for (int k = 0; k < 4; k++) acc[i][j][k] = 0.f;

    const bf16* pA0 = A + (size_t)(bm + r0)*K + s0*8;
    const bf16* pA1 = A + (size_t)(bm + r0 + 64)*K + s0*8;
    const bf16* pW0 = W + (size_t)(bn + r0)*K + s0*8;
    const bf16* pW1 = W + (size_t)(bn + r0 + 64)*K + s0*8;

    const uint32_t w0 = (r0*SKW + s0*4)*4;          // byte offset in plane
    const uint32_t w1 = ((r0+64)*SKW + s0*4)*4;

    auto issue = [&](int c){
        uint32_t b = sb + (c & 1)*(4*GPLANE*4);
        size_t go = (size_t)c*32;
        cp16(b + 0*GPLANE*4 + w0, pA0 + go);
        cp16(b + 0*GPLANE*4 + w1, pA1 + go);
        cp16(b + 1*GPLANE*4 + w0, pA0 + ACT + go);
        cp16(b + 1*GPLANE*4 + w1, pA1 + ACT + go);
        cp16(b + 2*GPLANE*4 + w0, pW0 + go);
        cp16(b + 2*GPLANE*4 + w1, pW1 + go);
        cp16(b + 3*GPLANE*4 + w0, pW0 + EE + go);
        cp16(b + 3*GPLANE*4 + w1, pW1 + EE + go);
        CP_COMMIT();
    };

    const int nch = K >> 5;
    issue(0);
    for (int c = 0; c < nch; c++){
        CP_WAIT0();
        __syncthreads();                      // chunk c visible; mma(c-1) done in all warps
        if (c + 1 < nch) issue(c + 1);        // fills other buffer (safe: mma(c-1) complete)
        uint32_t* cur = smw + (c & 1)*4*GPLANE;
        mma_chunk<4,4>(acc, cur, cur + GPLANE, cur + 2*GPLANE, cur + 3*GPLANE, wm, wn, lane);
    }

    const int r = lane >> 2, cl = (lane & 3)*2;
#pragma unroll
    for (int mi = 0; mi < 4; mi++){
#pragma unroll
        for (int ni = 0; ni < 4; ni++){
            int row = bm + wm + mi*16 + r;
            int col = bn + wn + ni*8 + cl;
            float2 bv = *(const float2*)(bias + col);
            float2 o0, o1;
            o0.x = acc[mi][ni][0] + bv.x; o0.y = acc[mi][ni][1] + bv.y;
            o1.x = acc[mi][ni][2] + bv.x; o1.y = acc[mi][ni][3] + bv.y;
            if (OB){
                store_hl(Ch, Ch + ACT, (size_t)row*N + col, o0);
                store_hl(Ch, Ch + ACT, (size_t)(row+8)*N + col, o1);
            } else {
                *(float2*)(C + (size_t)row*N + col)     = o0;
                *(float2*)(C + (size_t)(row+8)*N + col) = o1;
            }
        }
    }
}

// ============================================================
// scores: raw masked fp32 (unchanged structure)
// ============================================================
__global__ __launch_bounds__(256, 1)
void scores_mma(const bf16* __restrict__ Q2, const bf16* __restrict__ K2,
                const int* __restrict__ mask, float* __restrict__ attn)
{
    extern __shared__ __align__(16) uint32_t smw[];
    uint32_t* sQh = smw;
    uint32_t* sQl = smw + SCPLANE;
    uint32_t* sKh = smw + 2*SCPLANE;
    uint32_t* sKl = smw + 3*SCPLANE;

    const int tid = threadIdx.x, wid = tid >> 5, lane = tid & 31;
    const int wm = (wid >> 2)*64, wn = (wid & 3)*32;
    const int bh = blockIdx.z, b = bh >> 4, h = bh & 15;
    const int bm = blockIdx.y*128, bn = blockIdx.x*128;

#pragma unroll
    for (int i = 0; i < 4; i++){
        int u = tid + i*256;
        int ch = u >> 9, row = (u >> 2) & 127, s = u & 3;
        size_t gq = ((size_t)(b*SEQ + bm + row))*EMB + h*DH + ch*32 + s*8;
        size_t gk = ((size_t)(b*SEQ + bn + row))*EMB + h*DH + ch*32 + s*8;
        int wb = ch*GPLANE + row*SKW + s*4;
        *(uint4*)(sQh + wb) = *(const uint4*)(Q2 + gq);
        *(uint4*)(sQl + wb) = *(const uint4*)(Q2 + ACT + gq);
        *(uint4*)(sKh + wb) = *(const uint4*)(K2 + gk);
        *(uint4*)(sKl + wb) = *(const uint4*)(K2 + ACT + gk);
    }
    __syncthreads();

    float acc[4][4][4];
#pragma unroll
    for (int i = 0; i < 4; i++)
#pragma unroll
        for (int j = 0; j < 4; j++)
#pragma unroll
            for (int k = 0; k < 4; k++) acc[i][j][k] = 0.f;

#pragma unroll
    for (int ch = 0; ch < 2; ch++)
        mma_chunk<4,4>(acc, sQh + ch*GPLANE, sQl + ch*GPLANE,
                       sKh + ch*GPLANE, sKl + ch*GPLANE, wm, wn, lane);

    const int r = lane >> 2, cl = (lane & 3)*2;
    float* out = attn + (size_t)bh*SS;
#pragma unroll
    for (int mi = 0; mi < 4; mi++){
#pragma unroll
        for (int ni = 0; ni < 4; ni++){
            int row = bm + wm + mi*16 + r;
            int col = bn + wn + ni*8 + cl;
#pragma unroll
            for (int half = 0; half < 2; half++){
                int q = row + half*8;
                int2 m = *(const int2*)(mask + ((size_t)b*SEQ + q)*SEQ + col);
                float2 o;
                o.x = (m.x == 0) ? -1e9f : acc[mi][ni][half*2+0]*0.125f;
                o.y = (m.y == 0) ? -1e9f : acc[mi][ni][half*2+1]*0.125f;
                *(float2*)(out + (size_t)q*SEQ + col) = o;
            }
        }
    }
}

// ============================================================
// stats + head-average (unchanged)
// ============================================================
#define SM_STAT (256*68*4)

__global__ __launch_bounds__(256)
void stats_avg(const float* __restrict__ attn, float* __restrict__ avg,
               float2* __restrict__ stats)
{
    extern __shared__ float sp[];
    const int bq = blockIdx.x, b = bq >> 10, q = bq & 1023;
    const int t = threadIdx.x, h = t >> 4, part = t & 15;
    const float* row = attn + ((size_t)(b*NH + h)*SEQ + q)*SEQ + part*64;

    float4 v[16];
    float m = -3.0e38f;
#pragma unroll
    for (int i = 0; i < 16; i++){
        v[i] = ((const float4*)row)[i];
        m = fmaxf(m, fmaxf(fmaxf(v[i].x, v[i].y), fmaxf(v[i].z, v[i].w)));
    }
#pragma unroll
    for (int o = 8; o; o >>= 1) m = fmaxf(m, __shfl_xor_sync(0xffffffffu, m, o));

    float ssum = 0.f;
#pragma unroll
    for (int i = 0; i < 16; i++){
        v[i].x = __expf(v[i].x - m); v[i].y = __expf(v[i].y - m);
        v[i].z = __expf(v[i].z - m); v[i].w = __expf(v[i].w - m);
        ssum += v[i].x + v[i].y + v[i].z + v[i].w;
    }
#pragma unroll
    for (int o = 8; o; o >>= 1) ssum += __shfl_xor_sync(0xffffffffu, ssum, o);

    const float inv = 1.0f / ssum;
    if (part == 0)
        stats[(size_t)(b*NH + h)*SEQ + q] = make_float2(m, inv);

    float* slot = sp + (h*16 + part)*68;
#pragma unroll
    for (int i = 0; i < 16; i++){
        v[i].x *= inv; v[i].y *= inv; v[i].z *= inv; v[i].w *= inv;
        *(float4*)(slot + i*4) = v[i];
    }
    __syncthreads();

    const int part2 = t >> 4, j = t & 15;
    float4 a4 = make_float4(0.f, 0.f, 0.f, 0.f);
#pragma unroll
    for (int hh = 0; hh < 16; hh++){
        float4 p = *(const float4*)(sp + (hh*16 + part2)*68 + j*4);
        a4.x += p.x; a4.y += p.y; a4.z += p.z; a4.w += p.w;
    }
    a4.x *= 0.0625f; a4.y *= 0.0625f; a4.z *= 0.0625f; a4.w *= 0.0625f;
    *(float4*)(avg + ((size_t)b*SEQ + q)*SEQ + t*4) = a4;
}

// ============================================================
// ctx = softmax(P) @ V -> ctx bf16 hi/lo planes (unchanged structure)
// ============================================================
__global__ __launch_bounds__(256, 1)
void ctx_mma(const float* __restrict__ attn, const bf16* __restrict__ Vt2,
             const float2* __restrict__ stats, bf16* __restrict__ Ch)
{
    extern __shared__ __align__(16) uint32_t smw[];
    const int tid = threadIdx.x, wid = tid >> 5, lane = tid & 31;
    const int wm = (wid >> 2)*64, wn2 = (wid & 3)*16;
    const int bh = blockIdx.y, b = bh >> 4, h = bh & 15;
    const int bm = blockIdx.x*128;
    const float* Ab = attn + (size_t)bh*SS + (size_t)bm*SEQ;
    const bf16* BbH = Vt2 + ((size_t)b*EMB + h*DH)*SEQ;

    const int ar = tid >> 2, as = tid & 3;
    const float2 st0 = stats[(size_t)bh*SEQ + bm + ar];
    const float2 st1 = stats[(size_t)bh*SEQ + bm + ar + 64];

    float acc[4][2][4];
#pragma unroll
    for (int i = 0; i < 4; i++)
#pragma unroll
        for (int j = 0; j < 2; j++)
#pragma unroll
            for (int k = 0; k < 4; k++) acc[i][j][k] = 0.f;

    const float* pa0 = Ab + (size_t)ar*SEQ + as*8;
    const float* pa1 = Ab + (size_t)(ar + 64)*SEQ + as*8;
    const bf16* pbh = BbH + (size_t)ar*SEQ + as*8;

    float4 ra0, ra1, ra2, ra3;
    uint4 rbh, rbl;
    ra0 = *(const float4*)(pa0); ra1 = *(const float4*)(pa0+4);
    ra2 = *(const float4*)(pa1); ra3 = *(const float4*)(pa1+4);
    rbh = *(const uint4*)(pbh);  rbl = *(const uint4*)(pbh + ACT);

    auto store_buf = [&](uint32_t* bp){
        float4 t0, t1;
        t0.x = __expf(ra0.x - st0.x)*st0.y; t0.y = __expf(ra0.y - st0.x)*st0.y;
        t0.z = __expf(ra0.z - st0.x)*st0.y; t0.w = __expf(ra0.w - st0.x)*st0.y;
        t1.x = __expf(ra1.x - st0.x)*st0.y; t1.y = __expf(ra1.y - st0.x)*st0.y;
        t1.z = __expf(ra1.z - st0.x)*st0.y; t1.w = __expf(ra1.w - st0.x)*st0.y;
        uint4 hh, ll;
        cvt8v(t0, t1, hh, ll);
        *(uint4*)(bp + 0*GPLANE + ar*SKW + as*4) = hh;
        *(uint4*)(bp + 1*GPLANE + ar*SKW + as*4) = ll;
        t0.x = __expf(ra2.x - st1.x)*st1.y; t0.y = __expf(ra2.y - st1.x)*st1.y;
        t0.z = __expf(ra2.z - st1.x)*st1.y; t0.w = __expf(ra2.w - st1.x)*st1.y;
        t1.x = __expf(ra3.x - st1.x)*st1.y; t1.y = __expf(ra3.y - st1.x)*st1.y;
        t1.z = __expf(ra3.z - st1.x)*st1.y; t1.w = __expf(ra3.w - st1.x)*st1.y;
        cvt8v(t0, t1, hh, ll);
        *(uint4*)(bp + 0*GPLANE + (ar+64)*SKW + as*4) = hh;
        *(uint4*)(bp + 1*GPLANE + (ar+64)*SKW + as*4) = ll;
        *(uint4*)(bp + 2*GPLANE + ar*SKW + as*4) = rbh;
        *(uint4*)(bp + 2*GPLANE + BPLN + ar*SKW + as*4) = rbl;
    };
    store_buf(smw);
    __syncthreads();

    for (int c = 0; c < 32; c++){
        uint32_t* cur = smw + (c & 1)*CTXBUF;
        if (c < 31){
            int off = (c+1)*32;
            ra0 = *(const float4*)(pa0+off); ra1 = *(const float4*)(pa0+off+4);
            ra2 = *(const float4*)(pa1+off); ra3 = *(const float4*)(pa1+off+4);
            rbh = *(const uint4*)(pbh+off);  rbl = *(const uint4*)(pbh + ACT + off);
        }
        mma_chunk<4,2>(acc, cur, cur + GPLANE, cur + 2*GPLANE, cur + 2*GPLANE + BPLN,
                       wm, wn2, lane);
        if (c < 31) store_buf(smw + ((c+1) & 1)*CTXBUF);
        __syncthreads();
    }

    const int r = lane >> 2, cl = (lane & 3)*2;
#pragma unroll
    for (int mi = 0; mi < 4; mi++){
#pragma unroll
        for (int ni = 0; ni < 2; ni++){
            int row = bm + wm + mi*16 + r;
            int col = h*DH + wn2 + ni*8 + cl;
            float2 o0, o1;
            o0.x = acc[mi][ni][0]; o0.y = acc[mi][ni][1];
            o1.x = acc[mi][ni][2]; o1.y = acc[mi][ni][3];
            store_hl(Ch, Ch + ACT, ((size_t)b*SEQ + row)*EMB + col, o0);
            store_hl(Ch, Ch + ACT, ((size_t)b*SEQ + row + 8)*EMB + col, o1);
        }
    }
}

// ============================================================
// V transpose + hi/lo split
// ============================================================
__global__ void transpose_k(const float* __restrict__ V, bf16* __restrict__ Vt2)
{
    __shared__ float tile[32][33];
    const int b = blockIdx.z;
    const int e0 = blockIdx.x*32, s0 = blockIdx.y*32;
    const int tx = threadIdx.x, ty = threadIdx.y;
    const float* src = V + (size_t)b*SEQ*EMB;
#pragma unroll
    for (int i = 0; i < 32; i += 8)
        tile[ty + i][tx] = src[(size_t)(s0 + ty + i)*EMB + e0 + tx];
    __syncthreads();
#pragma unroll
    for (int i = 0; i < 32; i += 8){
        float v = tile[tx][ty + i];
        bf16 hb = __float2bfloat16(v);
        size_t off = ((size_t)b*EMB + e0 + ty + i)*SEQ + s0 + tx;
        Vt2[off] = hb;
        Vt2[ACT + off] = __float2bfloat16(v - __bfloat162float(hb));
    }
}

// ============================================================
extern "C" void kernel_launch(void* const* d_in, const int* in_sizes, int n_in,
                              void* d_out, int out_size)
{
    const float* query = (const float*)d_in[0];
    const float* key   = (const float*)d_in[1];
    const float* value = (const float*)d_in[2];
    const int*   mask  = (const int*)  d_in[3];
    const float* Wq = (const float*)d_in[4];
    const float* bq = (const float*)d_in[5];
    const float* Wk = (const float*)d_in[6];
    const float* bk = (const float*)d_in[7];
    const float* Wv = (const float*)d_in[8];
    const float* bv = (const float*)d_in[9];
    const float* Wo = (const float*)d_in[10];
    const float* bo = (const float*)d_in[11];

    float* out      = (float*)d_out;
    float* attn_avg = out + ACT;

    float *V, *ATT; float2* STATS;
    bf16 *QI, *KI, *VI, *WQ2, *WK2, *WV2, *WO2, *Q2, *K2, *VT2;
    cudaGetSymbolAddress((void**)&V,     g_V);
    cudaGetSymbolAddress((void**)&ATT,   g_attn);
    cudaGetSymbolAddress((void**)&STATS, g_stats);
    cudaGetSymbolAddress((void**)&QI,  g_qi);  cudaGetSymbolAddress((void**)&KI,  g_ki);
    cudaGetSymbolAddress((void**)&VI,  g_vi);
    cudaGetSymbolAddress((void**)&WQ2, g_Wq2); cudaGetSymbolAddress((void**)&WK2, g_Wk2);
    cudaGetSymbolAddress((void**)&WV2, g_Wv2); cudaGetSymbolAddress((void**)&WO2, g_Wo2);
    cudaGetSymbolAddress((void**)&Q2,  g_Q2);  cudaGetSymbolAddress((void**)&K2,  g_K2);
    cudaGetSymbolAddress((void**)&VT2, g_Vt2);

    const int SM_GEMMD = 2*4*GPLANE*4;   // 81920
    const int SM_SCOR  = 4*SCPLANE*4;    // 81920
    const int SM_CTXD  = 2*CTXBUF*4;     // 61440

    cudaFuncSetAttribute(gemm_plane<true>,  cudaFuncAttributeMaxDynamicSharedMemorySize, SM_GEMMD);
    cudaFuncSetAttribute(gemm_plane<false>, cudaFuncAttributeMaxDynamicSharedMemorySize, SM_GEMMD);
    cudaFuncSetAttribute(scores_mma, cudaFuncAttributeMaxDynamicSharedMemorySize, SM_SCOR);
    cudaFuncSetAttribute(ctx_mma,    cudaFuncAttributeMaxDynamicSharedMemorySize, SM_CTXD);
    cudaFuncSetAttribute(stats_avg,  cudaFuncAttributeMaxDynamicSharedMemorySize, SM_STAT);

    const int M = BATCH*SEQ;
    const int nact8 = (int)(ACT/8), nw8 = (int)(EE/8);

    split_act<<<dim3((nact8+255)/256, 3), 256>>>(query, key, value, QI, KI, VI, nact8);
    split_w  <<<dim3((nw8+255)/256, 4), 256>>>(Wq, Wk, Wv, Wo, WQ2, WK2, WV2, WO2, nw8);

    dim3 gproj(EMB/128, M/128);
    gemm_plane<true><<<gproj, 256, SM_GEMMD>>>(QI, WQ2, bq, nullptr, Q2, M, EMB, EMB);
    gemm_plane<true><<<gproj, 256, SM_GEMMD>>>(KI, WK2, bk, nullptr, K2, M, EMB, EMB);
    gemm_plane<false><<<gproj, 256, SM_GEMMD>>>(VI, WV2, bv, V, nullptr, M, EMB, EMB);

    transpose_k<<<dim3(EMB/32, SEQ/32, BATCH), dim3(32, 8)>>>(V, VT2);

    scores_mma<<<dim3(SEQ/128, SEQ/128, BH), 256, SM_SCOR>>>(Q2, K2, mask, ATT);

    stats_avg<<<BATCH*SEQ, 256, SM_STAT>>>(ATT, attn_avg, STATS);

    // ctx planes reuse Q2 (dead after scores)
    ctx_mma<<<dim3(SEQ/128, BH), 256, SM_CTXD>>>(ATT, VT2, STATS, Q2);

    gemm_plane<false><<<gproj, 256, SM_GEMMD>>>(Q2, WO2, bo, out, nullptr, M, EMB, EMB);
}